// round 13
// baseline (speedup 1.0000x reference)
#include <cuda_runtime.h>
#include <cuda_bf16.h>
#include <cuda_fp16.h>
#include <cstdint>

#define NN 100000
#define EMAXC 1700000

// ---------------- scratch (static device globals; no allocs) ----------------
__device__ uint32_t g_h1h[NN * 32];  // layer1 features, fp16x2 (64 cols)
__device__ uint32_t g_x1h[NN * 32];  // layer1 output, fp16x2 (64 cols)
__device__ uint32_t g_h2h[NN * 16];  // layer2 features, fp16x2 (32 cols)
__device__ float    g_as[NN];
__device__ float    g_ad[NN];
__device__ int      g_deg[NN];
__device__ int      g_rowptr[NN + 1];
__device__ int      g_cur[NN];
__device__ int      g_blk[128];
__device__ int      g_esrc[EMAXC];
__device__ uint4    g_bf[4096];      // W1 fragments [kk16][n64][tig4]
__device__ uint4    g_bf2[512];      // W2 fragments [kk4][n32][tig4]

typedef unsigned long long u64;

__device__ __forceinline__ void mma_bf16(float* c, uint32_t a0, uint32_t a1,
                                         uint32_t a2, uint32_t a3,
                                         uint32_t b0, uint32_t b1) {
    asm volatile(
        "mma.sync.aligned.m16n8k16.row.col.f32.bf16.bf16.f32 "
        "{%0,%1,%2,%3}, {%4,%5,%6,%7}, {%8,%9}, {%0,%1,%2,%3};"
        : "+f"(c[0]), "+f"(c[1]), "+f"(c[2]), "+f"(c[3])
        : "r"(a0), "r"(a1), "r"(a2), "r"(a3), "r"(b0), "r"(b1));
}
__device__ __forceinline__ void mma_f16(float* c, uint32_t a0, uint32_t a1,
                                        uint32_t a2, uint32_t a3,
                                        uint32_t b0, uint32_t b1) {
    asm volatile(
        "mma.sync.aligned.m16n8k16.row.col.f32.f16.f16.f32 "
        "{%0,%1,%2,%3}, {%4,%5,%6,%7}, {%8,%9}, {%0,%1,%2,%3};"
        : "+f"(c[0]), "+f"(c[1]), "+f"(c[2]), "+f"(c[3])
        : "r"(a0), "r"(a1), "r"(a2), "r"(a3), "r"(b0), "r"(b1));
}

__device__ __forceinline__ uint32_t bfhi2(float x, float y) {
    __nv_bfloat162 h = __floats2bfloat162_rn(x, y);
    return *(uint32_t*)&h;
}
__device__ __forceinline__ uint32_t bflo2(float x, float y, uint32_t hi) {
    __nv_bfloat162 h = *(__nv_bfloat162*)&hi;
    float2 f = __bfloat1622float2(h);
    __nv_bfloat162 l = __floats2bfloat162_rn(x - f.x, y - f.y);
    return *(uint32_t*)&l;
}
__device__ __forceinline__ uint32_t fp16x2(float x, float y) {
    __half2 h = __floats2half2_rn(x, y);
    return *(uint32_t*)&h;
}
__device__ __forceinline__ uint32_t fp16lo2(float x, float y, uint32_t hi) {
    __half2 h = *(__half2*)&hi;
    float2 f = __half22float2(h);
    __half2 l = __floats2half2_rn(x - f.x, y - f.y);
    return *(uint32_t*)&l;
}
__device__ __forceinline__ float2 h2f(uint32_t u) {
    return __half22float2(*(__half2*)&u);
}

// precompute W1 fragments (bf16 hi/lo): idx = kk*256 + n*4 + tig
__global__ void preconv_b_kernel(const float* __restrict__ W,
                                 uint4* __restrict__ Bf) {
    int idx = blockIdx.x * 256 + threadIdx.x;
    if (idx >= 4096) return;
    int tig = idx & 3, n = (idx >> 2) & 63, kk = idx >> 8;
    int k = kk * 16 + 2 * tig;
    float w00 = __ldg(&W[(size_t)k * 64 + n]);
    float w01 = __ldg(&W[(size_t)(k + 1) * 64 + n]);
    float w10 = __ldg(&W[(size_t)(k + 8) * 64 + n]);
    float w11 = __ldg(&W[(size_t)(k + 9) * 64 + n]);
    uint4 o;
    o.x = bfhi2(w00, w01);
    o.y = bfhi2(w10, w11);
    o.z = bflo2(w00, w01, o.x);
    o.w = bflo2(w10, w11, o.y);
    Bf[idx] = o;
}

// precompute W2 fragments (fp16 hi/lo): idx = kk*128 + n*4 + tig; W2 [64,32]
__global__ void preconv_b2_kernel(const float* __restrict__ W,
                                  uint4* __restrict__ Bf) {
    int idx = threadIdx.x;
    if (idx >= 512) return;
    int tig = idx & 3, n = (idx >> 2) & 31, kk = idx >> 7;
    int k = kk * 16 + 2 * tig;
    float w00 = __ldg(&W[(size_t)k * 32 + n]);
    float w01 = __ldg(&W[(size_t)(k + 1) * 32 + n]);
    float w10 = __ldg(&W[(size_t)(k + 8) * 32 + n]);
    float w11 = __ldg(&W[(size_t)(k + 9) * 32 + n]);
    uint4 o;
    o.x = fp16x2(w00, w01);
    o.y = fp16x2(w10, w11);
    o.z = fp16lo2(w00, w01, o.x);
    o.w = fp16lo2(w10, w11, o.y);
    Bf[idx] = o;
}

// ==== gemm1 (16 rows/warp, bf16 split): h1h = fp16(x @ W1) + alphas ========
__global__ void __launch_bounds__(256, 4)
gemm1_mma_kernel(const float* __restrict__ A,   // [M,256]
                 const uint4* __restrict__ Bf,
                 uint32_t* __restrict__ Ch,     // [M,32] fp16x2
                 int M,
                 const float* __restrict__ av, const float* __restrict__ bv,
                 float* __restrict__ as_out, float* __restrict__ ad_out) {
    const int tid = threadIdx.x;
    const int wid = tid >> 5, lane = tid & 31;
    const int gid = lane >> 2, tig = lane & 3;
    const int rowBase = blockIdx.x * 128;

    const int grLo = rowBase + wid * 16 + gid;
    const int grHi = grLo + 8;
    const float* a0p = A + (size_t)min(grLo, M - 1) * 256 + 2 * tig;
    const float* a1p = A + (size_t)min(grHi, M - 1) * 256 + 2 * tig;

    float acc[8][4];
#pragma unroll
    for (int t = 0; t < 8; t++)
#pragma unroll
        for (int j = 0; j < 4; j++) acc[t][j] = 0.f;

#pragma unroll 4
    for (int kk = 0; kk < 16; kk++) {
        float2 v00 = __ldg((const float2*)(a0p + kk * 16));
        float2 v01 = __ldg((const float2*)(a0p + kk * 16 + 8));
        float2 v10 = __ldg((const float2*)(a1p + kk * 16));
        float2 v11 = __ldg((const float2*)(a1p + kk * 16 + 8));
        uint32_t ah0 = bfhi2(v00.x, v00.y), ah1 = bfhi2(v10.x, v10.y);
        uint32_t ah2 = bfhi2(v01.x, v01.y), ah3 = bfhi2(v11.x, v11.y);
        uint32_t al0 = bflo2(v00.x, v00.y, ah0), al1 = bflo2(v10.x, v10.y, ah1);
        uint32_t al2 = bflo2(v01.x, v01.y, ah2), al3 = bflo2(v11.x, v11.y, ah3);
        const uint4* bp = Bf + kk * 256 + gid * 4 + tig;
#pragma unroll
        for (int nt = 0; nt < 8; nt++) {
            uint4 b = __ldg(bp + nt * 32);
            mma_bf16(acc[nt], ah0, ah1, ah2, ah3, b.x, b.y);  // hi*hi
            mma_bf16(acc[nt], ah0, ah1, ah2, ah3, b.z, b.w);  // hi*lo
            mma_bf16(acc[nt], al0, al1, al2, al3, b.x, b.y);  // lo*hi
        }
    }

    float sLo = 0.f, dLo = 0.f, sHi = 0.f, dHi = 0.f;
#pragma unroll
    for (int nt = 0; nt < 8; nt++) {
        int col = nt * 8 + 2 * tig;
        float a0 = __ldg(&av[col]), a1 = __ldg(&av[col + 1]);
        float b0 = __ldg(&bv[col]), b1 = __ldg(&bv[col + 1]);
        if (grLo < M)
            Ch[(size_t)grLo * 32 + nt * 4 + tig] = fp16x2(acc[nt][0], acc[nt][1]);
        if (grHi < M)
            Ch[(size_t)grHi * 32 + nt * 4 + tig] = fp16x2(acc[nt][2], acc[nt][3]);
        sLo += acc[nt][0] * a0 + acc[nt][1] * a1;
        dLo += acc[nt][0] * b0 + acc[nt][1] * b1;
        sHi += acc[nt][2] * a0 + acc[nt][3] * a1;
        dHi += acc[nt][2] * b0 + acc[nt][3] * b1;
    }
#pragma unroll
    for (int off = 1; off < 4; off <<= 1) {
        sLo += __shfl_xor_sync(0xffffffffu, sLo, off);
        dLo += __shfl_xor_sync(0xffffffffu, dLo, off);
        sHi += __shfl_xor_sync(0xffffffffu, sHi, off);
        dHi += __shfl_xor_sync(0xffffffffu, dHi, off);
    }
    if (tig == 0) {
        if (grLo < M) { as_out[grLo] = sLo; ad_out[grLo] = dLo; }
        if (grHi < M) { as_out[grHi] = sHi; ad_out[grHi] = dHi; }
    }
}

// ==== gemm2 (fp16 exact MMA): h2h = fp16(x1h @ W2) + alphas ================
__global__ void __launch_bounds__(256)
gemm2_mma_kernel(const uint32_t* __restrict__ A,  // [M,32] fp16x2 (64 cols)
                 const uint4* __restrict__ Bf2,
                 uint32_t* __restrict__ Ch,       // [M,16] fp16x2 (32 cols)
                 int M,
                 const float* __restrict__ av, const float* __restrict__ bv,
                 float* __restrict__ as_out, float* __restrict__ ad_out) {
    const int tid = threadIdx.x;
    const int wid = tid >> 5, lane = tid & 31;
    const int gid = lane >> 2, tig = lane & 3;
    const int rowBase = blockIdx.x * 128;

    const int grLo = rowBase + wid * 16 + gid;
    const int grHi = grLo + 8;
    const uint32_t* a0p = A + (size_t)min(grLo, M - 1) * 32 + tig;
    const uint32_t* a1p = A + (size_t)min(grHi, M - 1) * 32 + tig;

    float acc[4][4];
#pragma unroll
    for (int t = 0; t < 4; t++)
#pragma unroll
        for (int j = 0; j < 4; j++) acc[t][j] = 0.f;

#pragma unroll
    for (int kk = 0; kk < 4; kk++) {
        uint32_t a0 = __ldg(a0p + kk * 8);
        uint32_t a2 = __ldg(a0p + kk * 8 + 4);
        uint32_t a1 = __ldg(a1p + kk * 8);
        uint32_t a3 = __ldg(a1p + kk * 8 + 4);
        const uint4* bp = Bf2 + kk * 128 + gid * 4 + tig;
#pragma unroll
        for (int nt = 0; nt < 4; nt++) {
            uint4 b = __ldg(bp + nt * 32);
            mma_f16(acc[nt], a0, a1, a2, a3, b.x, b.y);  // x1 * W2_hi
            mma_f16(acc[nt], a0, a1, a2, a3, b.z, b.w);  // x1 * W2_lo
        }
    }

    float sLo = 0.f, dLo = 0.f, sHi = 0.f, dHi = 0.f;
#pragma unroll
    for (int nt = 0; nt < 4; nt++) {
        int col = nt * 8 + 2 * tig;
        float a0 = __ldg(&av[col]), a1 = __ldg(&av[col + 1]);
        float b0 = __ldg(&bv[col]), b1 = __ldg(&bv[col + 1]);
        if (grLo < M)
            Ch[(size_t)grLo * 16 + nt * 4 + tig] = fp16x2(acc[nt][0], acc[nt][1]);
        if (grHi < M)
            Ch[(size_t)grHi * 16 + nt * 4 + tig] = fp16x2(acc[nt][2], acc[nt][3]);
        sLo += acc[nt][0] * a0 + acc[nt][1] * a1;
        dLo += acc[nt][0] * b0 + acc[nt][1] * b1;
        sHi += acc[nt][2] * a0 + acc[nt][3] * a1;
        dHi += acc[nt][2] * b0 + acc[nt][3] * b1;
    }
#pragma unroll
    for (int off = 1; off < 4; off <<= 1) {
        sLo += __shfl_xor_sync(0xffffffffu, sLo, off);
        dLo += __shfl_xor_sync(0xffffffffu, dLo, off);
        sHi += __shfl_xor_sync(0xffffffffu, sHi, off);
        dHi += __shfl_xor_sync(0xffffffffu, dHi, off);
    }
    if (tig == 0) {
        if (grLo < M) { as_out[grLo] = sLo; ad_out[grLo] = dLo; }
        if (grHi < M) { as_out[grHi] = sHi; ad_out[grHi] = dHi; }
    }
}

// ======================= CSR build =======================
// hist over REAL edges only (self-loops folded into the scan as +1).
// Vectorized: 4 edges per thread via int4.
__global__ void hist_kernel(const int* __restrict__ ei, int E,
                            int* __restrict__ deg) {
    int t = blockIdx.x * blockDim.x + threadIdx.x;
    int e4 = t * 4;
    if (e4 + 3 < E) {
        int4 d = __ldg((const int4*)(ei + E + e4));
        atomicAdd(&deg[d.x], 1);
        atomicAdd(&deg[d.y], 1);
        atomicAdd(&deg[d.z], 1);
        atomicAdd(&deg[d.w], 1);
    } else {
        for (int e = e4; e < E; e++) atomicAdd(&deg[__ldg(&ei[E + e])], 1);
    }
}

__global__ void scan_block_kernel(const int* __restrict__ deg,
                                  int* __restrict__ rowptr,
                                  int* __restrict__ blk, int n) {
    __shared__ int sh[1024];
    int i = blockIdx.x * 1024 + threadIdx.x;
    int v = (i < n) ? deg[i] + 1 : 0;   // +1 = self loop
    sh[threadIdx.x] = v;
    __syncthreads();
#pragma unroll
    for (int off = 1; off < 1024; off <<= 1) {
        int t = (threadIdx.x >= off) ? sh[threadIdx.x - off] : 0;
        __syncthreads();
        sh[threadIdx.x] += t;
        __syncthreads();
    }
    if (i < n) rowptr[i + 1] = sh[threadIdx.x];
    if (threadIdx.x == 1023) blk[blockIdx.x] = sh[1023];
}

__global__ void scan_tops_kernel(int* __restrict__ blk, int nb) {
    __shared__ int sh[128];
    int v = (threadIdx.x < nb) ? blk[threadIdx.x] : 0;
    sh[threadIdx.x] = v;
    __syncthreads();
#pragma unroll
    for (int off = 1; off < 128; off <<= 1) {
        int t = (threadIdx.x >= off) ? sh[threadIdx.x - off] : 0;
        __syncthreads();
        sh[threadIdx.x] += t;
        __syncthreads();
    }
    if (threadIdx.x < nb)
        blk[threadIdx.x] = (threadIdx.x == 0) ? 0 : sh[threadIdx.x - 1];
}

__global__ void scan_add_kernel(int* __restrict__ rowptr,
                                const int* __restrict__ blk,
                                const int* __restrict__ deg,
                                int* __restrict__ cur, int n) {
    int i = blockIdx.x * 1024 + threadIdx.x;
    if (i >= n) return;
    int v = rowptr[i + 1] + blk[i / 1024];
    rowptr[i + 1] = v;
    cur[i] = v - (deg[i] + 1);   // +1 = self loop
    if (i == 0) rowptr[0] = 0;
}

// scatter: 2 real edges per thread (int2); threads past E/2 place self loops
__global__ void scatter_kernel(const int* __restrict__ ei, int E, int N,
                               int* __restrict__ cur, int* __restrict__ esrc) {
    int t = blockIdx.x * blockDim.x + threadIdx.x;
    int half = (E + 1) >> 1;
    if (t < half) {
        int e2 = t * 2;
        if (e2 + 1 < E) {
            int2 s = __ldg((const int2*)(ei + e2));
            int2 d = __ldg((const int2*)(ei + E + e2));
            esrc[atomicAdd(&cur[d.x], 1)] = s.x;
            esrc[atomicAdd(&cur[d.y], 1)] = s.y;
        } else if (e2 < E) {
            int s = __ldg(&ei[e2]), d = __ldg(&ei[E + e2]);
            esrc[atomicAdd(&cur[d], 1)] = s;
        }
    } else {
        int i = t - half;   // self loop for node i
        if (i < N) esrc[atomicAdd(&cur[i], 1)] = i;
    }
}

// ===== agg layer1: gather fp16 h1, softmax-avg, +bias, relu, emit fp16 x1 ===
__global__ void agg64_kernel(const int* __restrict__ rowptr,
                             const int* __restrict__ esrc,
                             const float* __restrict__ as,
                             const float* __restrict__ ad,
                             const uint32_t* __restrict__ hh,  // [n,32] fp16x2
                             const float* __restrict__ bias,
                             uint32_t* __restrict__ outh,      // [n,32] fp16x2
                             int n) {
    constexpr int G = 8, EPW = 4;
    int warp = (blockIdx.x * blockDim.x + threadIdx.x) >> 5;
    if (warp >= n) return;
    int lane = threadIdx.x & 31;
    int eslot = lane / G;
    int part = lane % G;

    int beg = __ldg(&rowptr[warp]);
    int end = __ldg(&rowptr[warp + 1]);
    float add = __ldg(&ad[warp]);

    float acc[8] = {0.f, 0.f, 0.f, 0.f, 0.f, 0.f, 0.f, 0.f};
    float den = 0.f;
    for (int i = beg + eslot; i < end; i += EPW) {
        int s = __ldg(&esrc[i]);
        float v = __ldg(&as[s]) + add;
        v = (v > 0.f) ? v : 0.2f * v;
        float w = __expf(v);
        uint4 hv = __ldg((const uint4*)(hh + (size_t)s * 32) + part);
        float2 f0 = h2f(hv.x), f1 = h2f(hv.y), f2 = h2f(hv.z), f3 = h2f(hv.w);
        acc[0] += w * f0.x; acc[1] += w * f0.y;
        acc[2] += w * f1.x; acc[3] += w * f1.y;
        acc[4] += w * f2.x; acc[5] += w * f2.y;
        acc[6] += w * f3.x; acc[7] += w * f3.y;
        den += w;
    }
#pragma unroll
    for (int off = G; off < 32; off <<= 1) {
#pragma unroll
        for (int j = 0; j < 8; j++)
            acc[j] += __shfl_xor_sync(0xffffffffu, acc[j], off);
        den += __shfl_xor_sync(0xffffffffu, den, off);
    }
    if (eslot == 0) {
        float inv = 1.f / den;
        float o[8];
#pragma unroll
        for (int j = 0; j < 8; j++)
            o[j] = fmaxf(acc[j] * inv + __ldg(&bias[part * 8 + j]), 0.f);
        uint4 pk;
        pk.x = fp16x2(o[0], o[1]);
        pk.y = fp16x2(o[2], o[3]);
        pk.z = fp16x2(o[4], o[5]);
        pk.w = fp16x2(o[6], o[7]);
        ((uint4*)(outh + (size_t)warp * 32))[part] = pk;
    }
}

// ===== agg layer2 + head: softmax-avg fp16 h2, +bias, relu, dot Wfc =========
__global__ void agg_final_kernel(const int* __restrict__ rowptr,
                                 const int* __restrict__ esrc,
                                 const float* __restrict__ as,
                                 const float* __restrict__ ad,
                                 const uint32_t* __restrict__ hh,  // [n,16]
                                 const float* __restrict__ b2,
                                 const float* __restrict__ Wfc,
                                 const float* __restrict__ bfc,
                                 float* __restrict__ out, int n) {
    constexpr int G = 4, EPW = 8;
    int warp = (blockIdx.x * blockDim.x + threadIdx.x) >> 5;
    if (warp >= n) return;
    int lane = threadIdx.x & 31;
    int eslot = lane / G;
    int part = lane % G;

    int beg = __ldg(&rowptr[warp]);
    int end = __ldg(&rowptr[warp + 1]);
    float add = __ldg(&ad[warp]);

    float acc[8] = {0.f, 0.f, 0.f, 0.f, 0.f, 0.f, 0.f, 0.f};
    float den = 0.f;
    for (int i = beg + eslot; i < end; i += EPW) {
        int s = __ldg(&esrc[i]);
        float v = __ldg(&as[s]) + add;
        v = (v > 0.f) ? v : 0.2f * v;
        float w = __expf(v);
        uint4 hv = __ldg((const uint4*)(hh + (size_t)s * 16) + part);
        float2 f0 = h2f(hv.x), f1 = h2f(hv.y), f2 = h2f(hv.z), f3 = h2f(hv.w);
        acc[0] += w * f0.x; acc[1] += w * f0.y;
        acc[2] += w * f1.x; acc[3] += w * f1.y;
        acc[4] += w * f2.x; acc[5] += w * f2.y;
        acc[6] += w * f3.x; acc[7] += w * f3.y;
        den += w;
    }
#pragma unroll
    for (int off = G; off < 32; off <<= 1) {
#pragma unroll
        for (int j = 0; j < 8; j++)
            acc[j] += __shfl_xor_sync(0xffffffffu, acc[j], off);
        den += __shfl_xor_sync(0xffffffffu, den, off);
    }
    if (eslot == 0) {  // lanes 0-3
        float inv = 1.f / den;
        float s = 0.f;
#pragma unroll
        for (int j = 0; j < 8; j++) {
            float v = fmaxf(acc[j] * inv + __ldg(&b2[part * 8 + j]), 0.f);
            s += v * __ldg(&Wfc[part * 8 + j]);
        }
        s += __shfl_xor_sync(0x0000000Fu, s, 1);
        s += __shfl_xor_sync(0x0000000Fu, s, 2);
        if (part == 0) out[warp] = s + __ldg(&bfc[0]);
    }
}

// ---------------- launch ----------------
extern "C" void kernel_launch(void* const* d_in, const int* in_sizes, int n_in,
                              void* d_out, int out_size) {
    const float* x   = (const float*)d_in[0];
    const int*   ei  = (const int*)d_in[1];
    const float* W1  = (const float*)d_in[2];
    const float* as1 = (const float*)d_in[3];
    const float* ad1 = (const float*)d_in[4];
    const float* b1  = (const float*)d_in[5];
    const float* W2  = (const float*)d_in[6];
    const float* as2 = (const float*)d_in[7];
    const float* ad2 = (const float*)d_in[8];
    const float* b2  = (const float*)d_in[9];
    const float* Wfc = (const float*)d_in[10];
    const float* bfc = (const float*)d_in[11];
    float* out = (float*)d_out;

    const int N = in_sizes[0] / 256;
    const int E = in_sizes[1] / 2;

    float *asb, *adb;
    uint32_t *h1h, *x1h, *h2h;
    int *deg, *rowptr, *cur, *blk, *esrc;
    uint4 *bf, *bf2;
    cudaGetSymbolAddress((void**)&h1h, g_h1h);
    cudaGetSymbolAddress((void**)&x1h, g_x1h);
    cudaGetSymbolAddress((void**)&h2h, g_h2h);
    cudaGetSymbolAddress((void**)&asb, g_as);
    cudaGetSymbolAddress((void**)&adb, g_ad);
    cudaGetSymbolAddress((void**)&deg, g_deg);
    cudaGetSymbolAddress((void**)&rowptr, g_rowptr);
    cudaGetSymbolAddress((void**)&cur, g_cur);
    cudaGetSymbolAddress((void**)&blk, g_blk);
    cudaGetSymbolAddress((void**)&esrc, g_esrc);
    cudaGetSymbolAddress((void**)&bf, g_bf);
    cudaGetSymbolAddress((void**)&bf2, g_bf2);

    static cudaStream_t s2 = nullptr;
    static cudaEvent_t evFork = nullptr, evJoin = nullptr;
    if (!s2) {
        cudaStreamCreateWithFlags(&s2, cudaStreamNonBlocking);
        cudaEventCreateWithFlags(&evFork, cudaEventDisableTiming);
        cudaEventCreateWithFlags(&evJoin, cudaEventDisableTiming);
    }

    const int T = 256;
    auto nb = [](long long n, int t) { return (int)((n + t - 1) / t); };
    const int nScanBlk = nb(N, 1024);

    // ---------- fork: CSR build starts on side stream ----------
    cudaEventRecord(evFork, 0);
    cudaStreamWaitEvent(s2, evFork, 0);
    cudaMemsetAsync(deg, 0, (size_t)N * sizeof(int), s2);
    hist_kernel<<<nb(((long long)E + 3) / 4, T), T, 0, s2>>>(ei, E, deg);  // 1
    scan_block_kernel<<<nScanBlk, 1024, 0, s2>>>(deg, rowptr, blk, N);     // 2

    // ---------- main stream: preconvert W1, then mma gemm1 (4th launch) ----
    preconv_b_kernel<<<16, 256>>>(W1, bf);                                 // 3
    gemm1_mma_kernel<<<nb(N, 128), 256>>>(x, bf, h1h, N, as1, ad1,
                                          asb, adb);                       // 4

    // ---------- side stream: rest of CSR build + W2 preconvert ----------
    scan_tops_kernel<<<1, 128, 0, s2>>>(blk, nScanBlk);
    scan_add_kernel<<<nScanBlk, 1024, 0, s2>>>(rowptr, blk, deg, cur, N);
    {
        long long scatterThreads = ((long long)E + 1) / 2 + N;
        scatter_kernel<<<nb(scatterThreads, T), T, 0, s2>>>(ei, E, N, cur, esrc);
    }
    preconv_b2_kernel<<<1, 512, 0, s2>>>(W2, bf2);
    cudaEventRecord(evJoin, s2);

    // ---------- join, then layer-1 aggregation (emits fp16 x1) ----------
    cudaStreamWaitEvent(0, evJoin, 0);
    agg64_kernel<<<nb((long long)N * 32, T), T>>>(rowptr, esrc, asb, adb,
                                                  h1h, b1, x1h, N);

    // ---------- layer 2: exact-fp16 MMA gemm, then fused agg+head ----------
    gemm2_mma_kernel<<<nb(N, 128), 256>>>(x1h, bf2, h2h, N, as2, ad2,
                                          asb, adb);
    agg_final_kernel<<<nb((long long)N * 32, T), T>>>(rowptr, esrc, asb, adb,
                                                      h2h, b2, Wfc, bfc,
                                                      out, N);
}

// round 14
// speedup vs baseline: 1.0107x; 1.0107x over previous
#include <cuda_runtime.h>
#include <cuda_bf16.h>
#include <cuda_fp16.h>
#include <cstdint>

#define NN 100000
#define EMAXC 1700000

// ---------------- scratch (static device globals; no allocs) ----------------
__device__ uint32_t g_h1h[NN * 32];  // layer1 features, fp16x2 (64 cols)
__device__ uint32_t g_x1h[NN * 32];  // layer1 output, fp16x2 (64 cols)
__device__ uint32_t g_h2h[NN * 16];  // layer2 features, fp16x2 (32 cols)
__device__ float    g_as[NN];
__device__ float    g_ad[NN];
__device__ int      g_deg[NN];
__device__ int      g_rowptr[NN + 1];
__device__ int      g_cur[NN];
__device__ int      g_blk[128];
__device__ int      g_esrc[EMAXC];
__device__ uint4    g_bf[4096];      // W1 fragments [kk16][n64][tig4]
__device__ uint4    g_bf2[512];      // W2 fragments [kk4][n32][tig4]

typedef unsigned long long u64;

__device__ __forceinline__ void mma_bf16(float* c, uint32_t a0, uint32_t a1,
                                         uint32_t a2, uint32_t a3,
                                         uint32_t b0, uint32_t b1) {
    asm volatile(
        "mma.sync.aligned.m16n8k16.row.col.f32.bf16.bf16.f32 "
        "{%0,%1,%2,%3}, {%4,%5,%6,%7}, {%8,%9}, {%0,%1,%2,%3};"
        : "+f"(c[0]), "+f"(c[1]), "+f"(c[2]), "+f"(c[3])
        : "r"(a0), "r"(a1), "r"(a2), "r"(a3), "r"(b0), "r"(b1));
}
__device__ __forceinline__ void mma_f16(float* c, uint32_t a0, uint32_t a1,
                                        uint32_t a2, uint32_t a3,
                                        uint32_t b0, uint32_t b1) {
    asm volatile(
        "mma.sync.aligned.m16n8k16.row.col.f32.f16.f16.f32 "
        "{%0,%1,%2,%3}, {%4,%5,%6,%7}, {%8,%9}, {%0,%1,%2,%3};"
        : "+f"(c[0]), "+f"(c[1]), "+f"(c[2]), "+f"(c[3])
        : "r"(a0), "r"(a1), "r"(a2), "r"(a3), "r"(b0), "r"(b1));
}

__device__ __forceinline__ uint32_t bfhi2(float x, float y) {
    __nv_bfloat162 h = __floats2bfloat162_rn(x, y);
    return *(uint32_t*)&h;
}
__device__ __forceinline__ uint32_t bflo2(float x, float y, uint32_t hi) {
    __nv_bfloat162 h = *(__nv_bfloat162*)&hi;
    float2 f = __bfloat1622float2(h);
    __nv_bfloat162 l = __floats2bfloat162_rn(x - f.x, y - f.y);
    return *(uint32_t*)&l;
}
__device__ __forceinline__ uint32_t fp16x2(float x, float y) {
    __half2 h = __floats2half2_rn(x, y);
    return *(uint32_t*)&h;
}
__device__ __forceinline__ uint32_t fp16lo2(float x, float y, uint32_t hi) {
    __half2 h = *(__half2*)&hi;
    float2 f = __half22float2(h);
    __half2 l = __floats2half2_rn(x - f.x, y - f.y);
    return *(uint32_t*)&l;
}
__device__ __forceinline__ float2 h2f(uint32_t u) {
    return __half22float2(*(__half2*)&u);
}

// precompute W1 fragments (bf16 hi/lo): idx = kk*256 + n*4 + tig
__global__ void preconv_b_kernel(const float* __restrict__ W,
                                 uint4* __restrict__ Bf) {
    int idx = blockIdx.x * 256 + threadIdx.x;
    if (idx >= 4096) return;
    int tig = idx & 3, n = (idx >> 2) & 63, kk = idx >> 8;
    int k = kk * 16 + 2 * tig;
    float w00 = __ldg(&W[(size_t)k * 64 + n]);
    float w01 = __ldg(&W[(size_t)(k + 1) * 64 + n]);
    float w10 = __ldg(&W[(size_t)(k + 8) * 64 + n]);
    float w11 = __ldg(&W[(size_t)(k + 9) * 64 + n]);
    uint4 o;
    o.x = bfhi2(w00, w01);
    o.y = bfhi2(w10, w11);
    o.z = bflo2(w00, w01, o.x);
    o.w = bflo2(w10, w11, o.y);
    Bf[idx] = o;
}

// precompute W2 fragments (fp16 hi/lo): idx = kk*128 + n*4 + tig; W2 [64,32]
__global__ void preconv_b2_kernel(const float* __restrict__ W,
                                  uint4* __restrict__ Bf) {
    int idx = threadIdx.x;
    if (idx >= 512) return;
    int tig = idx & 3, n = (idx >> 2) & 31, kk = idx >> 7;
    int k = kk * 16 + 2 * tig;
    float w00 = __ldg(&W[(size_t)k * 32 + n]);
    float w01 = __ldg(&W[(size_t)(k + 1) * 32 + n]);
    float w10 = __ldg(&W[(size_t)(k + 8) * 32 + n]);
    float w11 = __ldg(&W[(size_t)(k + 9) * 32 + n]);
    uint4 o;
    o.x = fp16x2(w00, w01);
    o.y = fp16x2(w10, w11);
    o.z = fp16lo2(w00, w01, o.x);
    o.w = fp16lo2(w10, w11, o.y);
    Bf[idx] = o;
}

// ==== gemm1 (16 rows/warp, bf16 split): h1h = fp16(x @ W1) + alphas ========
__global__ void __launch_bounds__(256)
gemm1_mma_kernel(const float* __restrict__ A,   // [M,256]
                 const uint4* __restrict__ Bf,
                 uint32_t* __restrict__ Ch,     // [M,32] fp16x2
                 int M,
                 const float* __restrict__ av, const float* __restrict__ bv,
                 float* __restrict__ as_out, float* __restrict__ ad_out) {
    const int tid = threadIdx.x;
    const int wid = tid >> 5, lane = tid & 31;
    const int gid = lane >> 2, tig = lane & 3;
    const int rowBase = blockIdx.x * 128;

    const int grLo = rowBase + wid * 16 + gid;
    const int grHi = grLo + 8;
    const float* a0p = A + (size_t)min(grLo, M - 1) * 256 + 2 * tig;
    const float* a1p = A + (size_t)min(grHi, M - 1) * 256 + 2 * tig;

    float acc[8][4];
#pragma unroll
    for (int t = 0; t < 8; t++)
#pragma unroll
        for (int j = 0; j < 4; j++) acc[t][j] = 0.f;

#pragma unroll 4
    for (int kk = 0; kk < 16; kk++) {
        float2 v00 = __ldg((const float2*)(a0p + kk * 16));
        float2 v01 = __ldg((const float2*)(a0p + kk * 16 + 8));
        float2 v10 = __ldg((const float2*)(a1p + kk * 16));
        float2 v11 = __ldg((const float2*)(a1p + kk * 16 + 8));
        uint32_t ah0 = bfhi2(v00.x, v00.y), ah1 = bfhi2(v10.x, v10.y);
        uint32_t ah2 = bfhi2(v01.x, v01.y), ah3 = bfhi2(v11.x, v11.y);
        uint32_t al0 = bflo2(v00.x, v00.y, ah0), al1 = bflo2(v10.x, v10.y, ah1);
        uint32_t al2 = bflo2(v01.x, v01.y, ah2), al3 = bflo2(v11.x, v11.y, ah3);
        const uint4* bp = Bf + kk * 256 + gid * 4 + tig;
#pragma unroll
        for (int nt = 0; nt < 8; nt++) {
            uint4 b = __ldg(bp + nt * 32);
            mma_bf16(acc[nt], ah0, ah1, ah2, ah3, b.x, b.y);  // hi*hi
            mma_bf16(acc[nt], ah0, ah1, ah2, ah3, b.z, b.w);  // hi*lo
            mma_bf16(acc[nt], al0, al1, al2, al3, b.x, b.y);  // lo*hi
        }
    }

    float sLo = 0.f, dLo = 0.f, sHi = 0.f, dHi = 0.f;
#pragma unroll
    for (int nt = 0; nt < 8; nt++) {
        int col = nt * 8 + 2 * tig;
        float a0 = __ldg(&av[col]), a1 = __ldg(&av[col + 1]);
        float b0 = __ldg(&bv[col]), b1 = __ldg(&bv[col + 1]);
        if (grLo < M)
            Ch[(size_t)grLo * 32 + nt * 4 + tig] = fp16x2(acc[nt][0], acc[nt][1]);
        if (grHi < M)
            Ch[(size_t)grHi * 32 + nt * 4 + tig] = fp16x2(acc[nt][2], acc[nt][3]);
        sLo += acc[nt][0] * a0 + acc[nt][1] * a1;
        dLo += acc[nt][0] * b0 + acc[nt][1] * b1;
        sHi += acc[nt][2] * a0 + acc[nt][3] * a1;
        dHi += acc[nt][2] * b0 + acc[nt][3] * b1;
    }
#pragma unroll
    for (int off = 1; off < 4; off <<= 1) {
        sLo += __shfl_xor_sync(0xffffffffu, sLo, off);
        dLo += __shfl_xor_sync(0xffffffffu, dLo, off);
        sHi += __shfl_xor_sync(0xffffffffu, sHi, off);
        dHi += __shfl_xor_sync(0xffffffffu, dHi, off);
    }
    if (tig == 0) {
        if (grLo < M) { as_out[grLo] = sLo; ad_out[grLo] = dLo; }
        if (grHi < M) { as_out[grHi] = sHi; ad_out[grHi] = dHi; }
    }
}

// ==== gemm2 (fp16 exact MMA): h2h = fp16(x1h @ W2) + alphas ================
__global__ void __launch_bounds__(256)
gemm2_mma_kernel(const uint32_t* __restrict__ A,  // [M,32] fp16x2 (64 cols)
                 const uint4* __restrict__ Bf2,
                 uint32_t* __restrict__ Ch,       // [M,16] fp16x2 (32 cols)
                 int M,
                 const float* __restrict__ av, const float* __restrict__ bv,
                 float* __restrict__ as_out, float* __restrict__ ad_out) {
    const int tid = threadIdx.x;
    const int wid = tid >> 5, lane = tid & 31;
    const int gid = lane >> 2, tig = lane & 3;
    const int rowBase = blockIdx.x * 128;

    const int grLo = rowBase + wid * 16 + gid;
    const int grHi = grLo + 8;
    const uint32_t* a0p = A + (size_t)min(grLo, M - 1) * 32 + tig;
    const uint32_t* a1p = A + (size_t)min(grHi, M - 1) * 32 + tig;

    float acc[4][4];
#pragma unroll
    for (int t = 0; t < 4; t++)
#pragma unroll
        for (int j = 0; j < 4; j++) acc[t][j] = 0.f;

#pragma unroll
    for (int kk = 0; kk < 4; kk++) {
        uint32_t a0 = __ldg(a0p + kk * 8);
        uint32_t a2 = __ldg(a0p + kk * 8 + 4);
        uint32_t a1 = __ldg(a1p + kk * 8);
        uint32_t a3 = __ldg(a1p + kk * 8 + 4);
        const uint4* bp = Bf2 + kk * 128 + gid * 4 + tig;
#pragma unroll
        for (int nt = 0; nt < 4; nt++) {
            uint4 b = __ldg(bp + nt * 32);
            mma_f16(acc[nt], a0, a1, a2, a3, b.x, b.y);  // x1 * W2_hi
            mma_f16(acc[nt], a0, a1, a2, a3, b.z, b.w);  // x1 * W2_lo
        }
    }

    float sLo = 0.f, dLo = 0.f, sHi = 0.f, dHi = 0.f;
#pragma unroll
    for (int nt = 0; nt < 4; nt++) {
        int col = nt * 8 + 2 * tig;
        float a0 = __ldg(&av[col]), a1 = __ldg(&av[col + 1]);
        float b0 = __ldg(&bv[col]), b1 = __ldg(&bv[col + 1]);
        if (grLo < M)
            Ch[(size_t)grLo * 16 + nt * 4 + tig] = fp16x2(acc[nt][0], acc[nt][1]);
        if (grHi < M)
            Ch[(size_t)grHi * 16 + nt * 4 + tig] = fp16x2(acc[nt][2], acc[nt][3]);
        sLo += acc[nt][0] * a0 + acc[nt][1] * a1;
        dLo += acc[nt][0] * b0 + acc[nt][1] * b1;
        sHi += acc[nt][2] * a0 + acc[nt][3] * a1;
        dHi += acc[nt][2] * b0 + acc[nt][3] * b1;
    }
#pragma unroll
    for (int off = 1; off < 4; off <<= 1) {
        sLo += __shfl_xor_sync(0xffffffffu, sLo, off);
        dLo += __shfl_xor_sync(0xffffffffu, dLo, off);
        sHi += __shfl_xor_sync(0xffffffffu, sHi, off);
        dHi += __shfl_xor_sync(0xffffffffu, dHi, off);
    }
    if (tig == 0) {
        if (grLo < M) { as_out[grLo] = sLo; ad_out[grLo] = dLo; }
        if (grHi < M) { as_out[grHi] = sHi; ad_out[grHi] = dHi; }
    }
}

// ======================= CSR build =======================
// hist over REAL edges only (self-loops folded into the scan as +1).
__global__ void hist_kernel(const int* __restrict__ ei, int E,
                            int* __restrict__ deg) {
    int t = blockIdx.x * blockDim.x + threadIdx.x;
    int e4 = t * 4;
    if (e4 + 3 < E) {
        int4 d = __ldg((const int4*)(ei + E + e4));
        atomicAdd(&deg[d.x], 1);
        atomicAdd(&deg[d.y], 1);
        atomicAdd(&deg[d.z], 1);
        atomicAdd(&deg[d.w], 1);
    } else {
        for (int e = e4; e < E; e++) atomicAdd(&deg[__ldg(&ei[E + e])], 1);
    }
}

__global__ void scan_block_kernel(const int* __restrict__ deg,
                                  int* __restrict__ rowptr,
                                  int* __restrict__ blk, int n) {
    __shared__ int sh[1024];
    int i = blockIdx.x * 1024 + threadIdx.x;
    int v = (i < n) ? deg[i] + 1 : 0;   // +1 = self loop
    sh[threadIdx.x] = v;
    __syncthreads();
#pragma unroll
    for (int off = 1; off < 1024; off <<= 1) {
        int t = (threadIdx.x >= off) ? sh[threadIdx.x - off] : 0;
        __syncthreads();
        sh[threadIdx.x] += t;
        __syncthreads();
    }
    if (i < n) rowptr[i + 1] = sh[threadIdx.x];
    if (threadIdx.x == 1023) blk[blockIdx.x] = sh[1023];
}

__global__ void scan_tops_kernel(int* __restrict__ blk, int nb) {
    __shared__ int sh[128];
    int v = (threadIdx.x < nb) ? blk[threadIdx.x] : 0;
    sh[threadIdx.x] = v;
    __syncthreads();
#pragma unroll
    for (int off = 1; off < 128; off <<= 1) {
        int t = (threadIdx.x >= off) ? sh[threadIdx.x - off] : 0;
        __syncthreads();
        sh[threadIdx.x] += t;
        __syncthreads();
    }
    if (threadIdx.x < nb)
        blk[threadIdx.x] = (threadIdx.x == 0) ? 0 : sh[threadIdx.x - 1];
}

__global__ void scan_add_kernel(int* __restrict__ rowptr,
                                const int* __restrict__ blk,
                                const int* __restrict__ deg,
                                int* __restrict__ cur, int n) {
    int i = blockIdx.x * 1024 + threadIdx.x;
    if (i >= n) return;
    int v = rowptr[i + 1] + blk[i / 1024];
    rowptr[i + 1] = v;
    cur[i] = v - (deg[i] + 1);   // +1 = self loop
    if (i == 0) rowptr[0] = 0;
}

// scatter: 2 real edges per thread (int2); threads past E/2 place self loops
__global__ void scatter_kernel(const int* __restrict__ ei, int E, int N,
                               int* __restrict__ cur, int* __restrict__ esrc) {
    int t = blockIdx.x * blockDim.x + threadIdx.x;
    int half = (E + 1) >> 1;
    if (t < half) {
        int e2 = t * 2;
        if (e2 + 1 < E) {
            int2 s = __ldg((const int2*)(ei + e2));
            int2 d = __ldg((const int2*)(ei + E + e2));
            esrc[atomicAdd(&cur[d.x], 1)] = s.x;
            esrc[atomicAdd(&cur[d.y], 1)] = s.y;
        } else if (e2 < E) {
            int s = __ldg(&ei[e2]), d = __ldg(&ei[E + e2]);
            esrc[atomicAdd(&cur[d], 1)] = s;
        }
    } else {
        int i = t - half;   // self loop for node i
        if (i < N) esrc[atomicAdd(&cur[i], 1)] = i;
    }
}

// ===== agg layer1: gather fp16 h1, softmax-avg, +bias, relu, emit fp16 x1 ===
__global__ void agg64_kernel(const int* __restrict__ rowptr,
                             const int* __restrict__ esrc,
                             const float* __restrict__ as,
                             const float* __restrict__ ad,
                             const uint32_t* __restrict__ hh,  // [n,32] fp16x2
                             const float* __restrict__ bias,
                             uint32_t* __restrict__ outh,      // [n,32] fp16x2
                             int n) {
    constexpr int G = 8, EPW = 4;
    int warp = (blockIdx.x * blockDim.x + threadIdx.x) >> 5;
    if (warp >= n) return;
    int lane = threadIdx.x & 31;
    int eslot = lane / G;
    int part = lane % G;

    int beg = __ldg(&rowptr[warp]);
    int end = __ldg(&rowptr[warp + 1]);
    float add = __ldg(&ad[warp]);

    float acc[8] = {0.f, 0.f, 0.f, 0.f, 0.f, 0.f, 0.f, 0.f};
    float den = 0.f;
    for (int i = beg + eslot; i < end; i += EPW) {
        int s = __ldg(&esrc[i]);
        float v = __ldg(&as[s]) + add;
        v = (v > 0.f) ? v : 0.2f * v;
        float w = __expf(v);
        uint4 hv = __ldg((const uint4*)(hh + (size_t)s * 32) + part);
        float2 f0 = h2f(hv.x), f1 = h2f(hv.y), f2 = h2f(hv.z), f3 = h2f(hv.w);
        acc[0] += w * f0.x; acc[1] += w * f0.y;
        acc[2] += w * f1.x; acc[3] += w * f1.y;
        acc[4] += w * f2.x; acc[5] += w * f2.y;
        acc[6] += w * f3.x; acc[7] += w * f3.y;
        den += w;
    }
#pragma unroll
    for (int off = G; off < 32; off <<= 1) {
#pragma unroll
        for (int j = 0; j < 8; j++)
            acc[j] += __shfl_xor_sync(0xffffffffu, acc[j], off);
        den += __shfl_xor_sync(0xffffffffu, den, off);
    }
    if (eslot == 0) {
        float inv = 1.f / den;
        float o[8];
#pragma unroll
        for (int j = 0; j < 8; j++)
            o[j] = fmaxf(acc[j] * inv + __ldg(&bias[part * 8 + j]), 0.f);
        uint4 pk;
        pk.x = fp16x2(o[0], o[1]);
        pk.y = fp16x2(o[2], o[3]);
        pk.z = fp16x2(o[4], o[5]);
        pk.w = fp16x2(o[6], o[7]);
        ((uint4*)(outh + (size_t)warp * 32))[part] = pk;
    }
}

// ===== agg layer2 + head: softmax-avg fp16 h2, +bias, relu, dot Wfc =========
__global__ void agg_final_kernel(const int* __restrict__ rowptr,
                                 const int* __restrict__ esrc,
                                 const float* __restrict__ as,
                                 const float* __restrict__ ad,
                                 const uint32_t* __restrict__ hh,  // [n,16]
                                 const float* __restrict__ b2,
                                 const float* __restrict__ Wfc,
                                 const float* __restrict__ bfc,
                                 float* __restrict__ out, int n) {
    constexpr int G = 4, EPW = 8;
    int warp = (blockIdx.x * blockDim.x + threadIdx.x) >> 5;
    if (warp >= n) return;
    int lane = threadIdx.x & 31;
    int eslot = lane / G;
    int part = lane % G;

    int beg = __ldg(&rowptr[warp]);
    int end = __ldg(&rowptr[warp + 1]);
    float add = __ldg(&ad[warp]);

    float acc[8] = {0.f, 0.f, 0.f, 0.f, 0.f, 0.f, 0.f, 0.f};
    float den = 0.f;
    for (int i = beg + eslot; i < end; i += EPW) {
        int s = __ldg(&esrc[i]);
        float v = __ldg(&as[s]) + add;
        v = (v > 0.f) ? v : 0.2f * v;
        float w = __expf(v);
        uint4 hv = __ldg((const uint4*)(hh + (size_t)s * 16) + part);
        float2 f0 = h2f(hv.x), f1 = h2f(hv.y), f2 = h2f(hv.z), f3 = h2f(hv.w);
        acc[0] += w * f0.x; acc[1] += w * f0.y;
        acc[2] += w * f1.x; acc[3] += w * f1.y;
        acc[4] += w * f2.x; acc[5] += w * f2.y;
        acc[6] += w * f3.x; acc[7] += w * f3.y;
        den += w;
    }
#pragma unroll
    for (int off = G; off < 32; off <<= 1) {
#pragma unroll
        for (int j = 0; j < 8; j++)
            acc[j] += __shfl_xor_sync(0xffffffffu, acc[j], off);
        den += __shfl_xor_sync(0xffffffffu, den, off);
    }
    if (eslot == 0) {  // lanes 0-3
        float inv = 1.f / den;
        float s = 0.f;
#pragma unroll
        for (int j = 0; j < 8; j++) {
            float v = fmaxf(acc[j] * inv + __ldg(&b2[part * 8 + j]), 0.f);
            s += v * __ldg(&Wfc[part * 8 + j]);
        }
        s += __shfl_xor_sync(0x0000000Fu, s, 1);
        s += __shfl_xor_sync(0x0000000Fu, s, 2);
        if (part == 0) out[warp] = s + __ldg(&bfc[0]);
    }
}

// ---------------- launch ----------------
extern "C" void kernel_launch(void* const* d_in, const int* in_sizes, int n_in,
                              void* d_out, int out_size) {
    const float* x   = (const float*)d_in[0];
    const int*   ei  = (const int*)d_in[1];
    const float* W1  = (const float*)d_in[2];
    const float* as1 = (const float*)d_in[3];
    const float* ad1 = (const float*)d_in[4];
    const float* b1  = (const float*)d_in[5];
    const float* W2  = (const float*)d_in[6];
    const float* as2 = (const float*)d_in[7];
    const float* ad2 = (const float*)d_in[8];
    const float* b2  = (const float*)d_in[9];
    const float* Wfc = (const float*)d_in[10];
    const float* bfc = (const float*)d_in[11];
    float* out = (float*)d_out;

    const int N = in_sizes[0] / 256;
    const int E = in_sizes[1] / 2;

    float *asb, *adb;
    uint32_t *h1h, *x1h, *h2h;
    int *deg, *rowptr, *cur, *blk, *esrc;
    uint4 *bf, *bf2;
    cudaGetSymbolAddress((void**)&h1h, g_h1h);
    cudaGetSymbolAddress((void**)&x1h, g_x1h);
    cudaGetSymbolAddress((void**)&h2h, g_h2h);
    cudaGetSymbolAddress((void**)&asb, g_as);
    cudaGetSymbolAddress((void**)&adb, g_ad);
    cudaGetSymbolAddress((void**)&deg, g_deg);
    cudaGetSymbolAddress((void**)&rowptr, g_rowptr);
    cudaGetSymbolAddress((void**)&cur, g_cur);
    cudaGetSymbolAddress((void**)&blk, g_blk);
    cudaGetSymbolAddress((void**)&esrc, g_esrc);
    cudaGetSymbolAddress((void**)&bf, g_bf);
    cudaGetSymbolAddress((void**)&bf2, g_bf2);

    static cudaStream_t s2 = nullptr;
    static cudaEvent_t evFork = nullptr, evJoin = nullptr;
    if (!s2) {
        cudaStreamCreateWithFlags(&s2, cudaStreamNonBlocking);
        cudaEventCreateWithFlags(&evFork, cudaEventDisableTiming);
        cudaEventCreateWithFlags(&evJoin, cudaEventDisableTiming);
    }

    const int T = 256;
    auto nb = [](long long n, int t) { return (int)((n + t - 1) / t); };
    const int nScanBlk = nb(N, 1024);

    // ---------- fork: CSR build starts on side stream ----------
    cudaEventRecord(evFork, 0);
    cudaStreamWaitEvent(s2, evFork, 0);
    cudaMemsetAsync(deg, 0, (size_t)N * sizeof(int), s2);
    hist_kernel<<<nb(((long long)E + 3) / 4, T), T, 0, s2>>>(ei, E, deg);  // 1
    scan_block_kernel<<<nScanBlk, 1024, 0, s2>>>(deg, rowptr, blk, N);     // 2

    // ---------- main stream: preconvert W1, then mma gemm1 (4th launch) ----
    preconv_b_kernel<<<16, 256>>>(W1, bf);                                 // 3
    gemm1_mma_kernel<<<nb(N, 128), 256>>>(x, bf, h1h, N, as1, ad1,
                                          asb, adb);                       // 4

    // ---------- side stream: rest of CSR build + W2 preconvert ----------
    scan_tops_kernel<<<1, 128, 0, s2>>>(blk, nScanBlk);
    scan_add_kernel<<<nScanBlk, 1024, 0, s2>>>(rowptr, blk, deg, cur, N);
    {
        long long scatterThreads = ((long long)E + 1) / 2 + N;
        scatter_kernel<<<nb(scatterThreads, T), T, 0, s2>>>(ei, E, N, cur, esrc);
    }
    preconv_b2_kernel<<<1, 512, 0, s2>>>(W2, bf2);
    cudaEventRecord(evJoin, s2);

    // ---------- join, then layer-1 aggregation (emits fp16 x1) ----------
    cudaStreamWaitEvent(0, evJoin, 0);
    agg64_kernel<<<nb((long long)N * 32, T), T>>>(rowptr, esrc, asb, adb,
                                                  h1h, b1, x1h, N);

    // ---------- layer 2: exact-fp16 MMA gemm, then fused agg+head ----------
    gemm2_mma_kernel<<<nb(N, 128), 256>>>(x1h, bf2, h2h, N, as2, ad2,
                                          asb, adb);
    agg_final_kernel<<<nb((long long)N * 32, T), T>>>(rowptr, esrc, asb, adb,
                                                      h2h, b2, Wfc, bfc,
                                                      out, N);
}

// round 15
// speedup vs baseline: 1.0439x; 1.0328x over previous
#include <cuda_runtime.h>
#include <cuda_bf16.h>
#include <cuda_fp16.h>
#include <cstdint>

#define NN 100000
#define EMAXC 1700000

// ---------------- scratch (static device globals; no allocs) ----------------
__device__ uint32_t g_h1h[NN * 32];  // layer1 features, fp16x2 (64 cols)
__device__ uint32_t g_x1h[NN * 32];  // layer1 output, fp16x2 (64 cols)
__device__ uint32_t g_h2h[NN * 16];  // layer2 features, fp16x2 (32 cols)
__device__ float    g_as[NN];
__device__ float    g_ad[NN];
__device__ int      g_deg[NN];
__device__ int      g_rowptr[NN + 1];
__device__ int      g_cur[NN];
__device__ int      g_blk[128];
__device__ int      g_esrc[EMAXC];
__device__ uint4    g_bf[4096];      // W1 fragments (fp16 hi/lo) [kk16][n64][tig4]
__device__ uint4    g_bf2[512];      // W2 fragments (fp16 hi/lo) [kk4][n32][tig4]

typedef unsigned long long u64;

__device__ __forceinline__ void mma_f16(float* c, uint32_t a0, uint32_t a1,
                                        uint32_t a2, uint32_t a3,
                                        uint32_t b0, uint32_t b1) {
    asm volatile(
        "mma.sync.aligned.m16n8k16.row.col.f32.f16.f16.f32 "
        "{%0,%1,%2,%3}, {%4,%5,%6,%7}, {%8,%9}, {%0,%1,%2,%3};"
        : "+f"(c[0]), "+f"(c[1]), "+f"(c[2]), "+f"(c[3])
        : "r"(a0), "r"(a1), "r"(a2), "r"(a3), "r"(b0), "r"(b1));
}

__device__ __forceinline__ uint32_t fp16x2(float x, float y) {
    __half2 h = __floats2half2_rn(x, y);
    return *(uint32_t*)&h;
}
__device__ __forceinline__ uint32_t fp16lo2(float x, float y, uint32_t hi) {
    __half2 h = *(__half2*)&hi;
    float2 f = __half22float2(h);
    __half2 l = __floats2half2_rn(x - f.x, y - f.y);
    return *(uint32_t*)&l;
}
__device__ __forceinline__ float2 h2f(uint32_t u) {
    return __half22float2(*(__half2*)&u);
}

// precompute W1 fragments (fp16 hi/lo): idx = kk*256 + n*4 + tig
__global__ void preconv_b_kernel(const float* __restrict__ W,
                                 uint4* __restrict__ Bf) {
    int idx = blockIdx.x * 256 + threadIdx.x;
    if (idx >= 4096) return;
    int tig = idx & 3, n = (idx >> 2) & 63, kk = idx >> 8;
    int k = kk * 16 + 2 * tig;
    float w00 = __ldg(&W[(size_t)k * 64 + n]);
    float w01 = __ldg(&W[(size_t)(k + 1) * 64 + n]);
    float w10 = __ldg(&W[(size_t)(k + 8) * 64 + n]);
    float w11 = __ldg(&W[(size_t)(k + 9) * 64 + n]);
    uint4 o;
    o.x = fp16x2(w00, w01);
    o.y = fp16x2(w10, w11);
    o.z = fp16lo2(w00, w01, o.x);
    o.w = fp16lo2(w10, w11, o.y);
    Bf[idx] = o;
}

// precompute W2 fragments (fp16 hi/lo): idx = kk*128 + n*4 + tig; W2 [64,32]
__global__ void preconv_b2_kernel(const float* __restrict__ W,
                                  uint4* __restrict__ Bf) {
    int idx = threadIdx.x;
    if (idx >= 512) return;
    int tig = idx & 3, n = (idx >> 2) & 31, kk = idx >> 7;
    int k = kk * 16 + 2 * tig;
    float w00 = __ldg(&W[(size_t)k * 32 + n]);
    float w01 = __ldg(&W[(size_t)(k + 1) * 32 + n]);
    float w10 = __ldg(&W[(size_t)(k + 8) * 32 + n]);
    float w11 = __ldg(&W[(size_t)(k + 9) * 32 + n]);
    uint4 o;
    o.x = fp16x2(w00, w01);
    o.y = fp16x2(w10, w11);
    o.z = fp16lo2(w00, w01, o.x);
    o.w = fp16lo2(w10, w11, o.y);
    Bf[idx] = o;
}

// ==== gemm1 (16 rows/warp, A fp16 single, W fp16 hi/lo 2-pass) =============
__global__ void __launch_bounds__(256)
gemm1_mma_kernel(const float* __restrict__ A,   // [M,256]
                 const uint4* __restrict__ Bf,
                 uint32_t* __restrict__ Ch,     // [M,32] fp16x2
                 int M,
                 const float* __restrict__ av, const float* __restrict__ bv,
                 float* __restrict__ as_out, float* __restrict__ ad_out) {
    const int tid = threadIdx.x;
    const int wid = tid >> 5, lane = tid & 31;
    const int gid = lane >> 2, tig = lane & 3;
    const int rowBase = blockIdx.x * 128;

    const int grLo = rowBase + wid * 16 + gid;
    const int grHi = grLo + 8;
    const float* a0p = A + (size_t)min(grLo, M - 1) * 256 + 2 * tig;
    const float* a1p = A + (size_t)min(grHi, M - 1) * 256 + 2 * tig;

    float acc[8][4];
#pragma unroll
    for (int t = 0; t < 8; t++)
#pragma unroll
        for (int j = 0; j < 4; j++) acc[t][j] = 0.f;

#pragma unroll 4
    for (int kk = 0; kk < 16; kk++) {
        float2 v00 = __ldg((const float2*)(a0p + kk * 16));
        float2 v01 = __ldg((const float2*)(a0p + kk * 16 + 8));
        float2 v10 = __ldg((const float2*)(a1p + kk * 16));
        float2 v11 = __ldg((const float2*)(a1p + kk * 16 + 8));
        uint32_t a0 = fp16x2(v00.x, v00.y);
        uint32_t a1 = fp16x2(v10.x, v10.y);
        uint32_t a2 = fp16x2(v01.x, v01.y);
        uint32_t a3 = fp16x2(v11.x, v11.y);
        const uint4* bp = Bf + kk * 256 + gid * 4 + tig;
#pragma unroll
        for (int nt = 0; nt < 8; nt++) {
            uint4 b = __ldg(bp + nt * 32);
            mma_f16(acc[nt], a0, a1, a2, a3, b.x, b.y);  // a * W_hi
            mma_f16(acc[nt], a0, a1, a2, a3, b.z, b.w);  // a * W_lo
        }
    }

    float sLo = 0.f, dLo = 0.f, sHi = 0.f, dHi = 0.f;
#pragma unroll
    for (int nt = 0; nt < 8; nt++) {
        int col = nt * 8 + 2 * tig;
        float a0 = __ldg(&av[col]), a1 = __ldg(&av[col + 1]);
        float b0 = __ldg(&bv[col]), b1 = __ldg(&bv[col + 1]);
        if (grLo < M)
            Ch[(size_t)grLo * 32 + nt * 4 + tig] = fp16x2(acc[nt][0], acc[nt][1]);
        if (grHi < M)
            Ch[(size_t)grHi * 32 + nt * 4 + tig] = fp16x2(acc[nt][2], acc[nt][3]);
        sLo += acc[nt][0] * a0 + acc[nt][1] * a1;
        dLo += acc[nt][0] * b0 + acc[nt][1] * b1;
        sHi += acc[nt][2] * a0 + acc[nt][3] * a1;
        dHi += acc[nt][2] * b0 + acc[nt][3] * b1;
    }
#pragma unroll
    for (int off = 1; off < 4; off <<= 1) {
        sLo += __shfl_xor_sync(0xffffffffu, sLo, off);
        dLo += __shfl_xor_sync(0xffffffffu, dLo, off);
        sHi += __shfl_xor_sync(0xffffffffu, sHi, off);
        dHi += __shfl_xor_sync(0xffffffffu, dHi, off);
    }
    if (tig == 0) {
        if (grLo < M) { as_out[grLo] = sLo; ad_out[grLo] = dLo; }
        if (grHi < M) { as_out[grHi] = sHi; ad_out[grHi] = dHi; }
    }
}

// ==== gemm2 (fp16 exact MMA): h2h = fp16(x1h @ W2) + alphas ================
__global__ void __launch_bounds__(256)
gemm2_mma_kernel(const uint32_t* __restrict__ A,  // [M,32] fp16x2 (64 cols)
                 const uint4* __restrict__ Bf2,
                 uint32_t* __restrict__ Ch,       // [M,16] fp16x2 (32 cols)
                 int M,
                 const float* __restrict__ av, const float* __restrict__ bv,
                 float* __restrict__ as_out, float* __restrict__ ad_out) {
    const int tid = threadIdx.x;
    const int wid = tid >> 5, lane = tid & 31;
    const int gid = lane >> 2, tig = lane & 3;
    const int rowBase = blockIdx.x * 128;

    const int grLo = rowBase + wid * 16 + gid;
    const int grHi = grLo + 8;
    const uint32_t* a0p = A + (size_t)min(grLo, M - 1) * 32 + tig;
    const uint32_t* a1p = A + (size_t)min(grHi, M - 1) * 32 + tig;

    float acc[4][4];
#pragma unroll
    for (int t = 0; t < 4; t++)
#pragma unroll
        for (int j = 0; j < 4; j++) acc[t][j] = 0.f;

#pragma unroll
    for (int kk = 0; kk < 4; kk++) {
        uint32_t a0 = __ldg(a0p + kk * 8);
        uint32_t a2 = __ldg(a0p + kk * 8 + 4);
        uint32_t a1 = __ldg(a1p + kk * 8);
        uint32_t a3 = __ldg(a1p + kk * 8 + 4);
        const uint4* bp = Bf2 + kk * 128 + gid * 4 + tig;
#pragma unroll
        for (int nt = 0; nt < 4; nt++) {
            uint4 b = __ldg(bp + nt * 32);
            mma_f16(acc[nt], a0, a1, a2, a3, b.x, b.y);  // x1 * W2_hi
            mma_f16(acc[nt], a0, a1, a2, a3, b.z, b.w);  // x1 * W2_lo
        }
    }

    float sLo = 0.f, dLo = 0.f, sHi = 0.f, dHi = 0.f;
#pragma unroll
    for (int nt = 0; nt < 4; nt++) {
        int col = nt * 8 + 2 * tig;
        float a0 = __ldg(&av[col]), a1 = __ldg(&av[col + 1]);
        float b0 = __ldg(&bv[col]), b1 = __ldg(&bv[col + 1]);
        if (grLo < M)
            Ch[(size_t)grLo * 16 + nt * 4 + tig] = fp16x2(acc[nt][0], acc[nt][1]);
        if (grHi < M)
            Ch[(size_t)grHi * 16 + nt * 4 + tig] = fp16x2(acc[nt][2], acc[nt][3]);
        sLo += acc[nt][0] * a0 + acc[nt][1] * a1;
        dLo += acc[nt][0] * b0 + acc[nt][1] * b1;
        sHi += acc[nt][2] * a0 + acc[nt][3] * a1;
        dHi += acc[nt][2] * b0 + acc[nt][3] * b1;
    }
#pragma unroll
    for (int off = 1; off < 4; off <<= 1) {
        sLo += __shfl_xor_sync(0xffffffffu, sLo, off);
        dLo += __shfl_xor_sync(0xffffffffu, dLo, off);
        sHi += __shfl_xor_sync(0xffffffffu, sHi, off);
        dHi += __shfl_xor_sync(0xffffffffu, dHi, off);
    }
    if (tig == 0) {
        if (grLo < M) { as_out[grLo] = sLo; ad_out[grLo] = dLo; }
        if (grHi < M) { as_out[grHi] = sHi; ad_out[grHi] = dHi; }
    }
}

// ======================= CSR build =======================
__global__ void hist_kernel(const int* __restrict__ ei, int E,
                            int* __restrict__ deg) {
    int t = blockIdx.x * blockDim.x + threadIdx.x;
    int e4 = t * 4;
    if (e4 + 3 < E) {
        int4 d = __ldg((const int4*)(ei + E + e4));
        atomicAdd(&deg[d.x], 1);
        atomicAdd(&deg[d.y], 1);
        atomicAdd(&deg[d.z], 1);
        atomicAdd(&deg[d.w], 1);
    } else {
        for (int e = e4; e < E; e++) atomicAdd(&deg[__ldg(&ei[E + e])], 1);
    }
}

__global__ void scan_block_kernel(const int* __restrict__ deg,
                                  int* __restrict__ rowptr,
                                  int* __restrict__ blk, int n) {
    __shared__ int sh[1024];
    int i = blockIdx.x * 1024 + threadIdx.x;
    int v = (i < n) ? deg[i] + 1 : 0;   // +1 = self loop
    sh[threadIdx.x] = v;
    __syncthreads();
#pragma unroll
    for (int off = 1; off < 1024; off <<= 1) {
        int t = (threadIdx.x >= off) ? sh[threadIdx.x - off] : 0;
        __syncthreads();
        sh[threadIdx.x] += t;
        __syncthreads();
    }
    if (i < n) rowptr[i + 1] = sh[threadIdx.x];
    if (threadIdx.x == 1023) blk[blockIdx.x] = sh[1023];
}

__global__ void scan_tops_kernel(int* __restrict__ blk, int nb) {
    __shared__ int sh[128];
    int v = (threadIdx.x < nb) ? blk[threadIdx.x] : 0;
    sh[threadIdx.x] = v;
    __syncthreads();
#pragma unroll
    for (int off = 1; off < 128; off <<= 1) {
        int t = (threadIdx.x >= off) ? sh[threadIdx.x - off] : 0;
        __syncthreads();
        sh[threadIdx.x] += t;
        __syncthreads();
    }
    if (threadIdx.x < nb)
        blk[threadIdx.x] = (threadIdx.x == 0) ? 0 : sh[threadIdx.x - 1];
}

__global__ void scan_add_kernel(int* __restrict__ rowptr,
                                const int* __restrict__ blk,
                                const int* __restrict__ deg,
                                int* __restrict__ cur, int n) {
    int i = blockIdx.x * 1024 + threadIdx.x;
    if (i >= n) return;
    int v = rowptr[i + 1] + blk[i / 1024];
    rowptr[i + 1] = v;
    cur[i] = v - (deg[i] + 1);   // +1 = self loop
    if (i == 0) rowptr[0] = 0;
}

__global__ void scatter_kernel(const int* __restrict__ ei, int E, int N,
                               int* __restrict__ cur, int* __restrict__ esrc) {
    int t = blockIdx.x * blockDim.x + threadIdx.x;
    int half = (E + 1) >> 1;
    if (t < half) {
        int e2 = t * 2;
        if (e2 + 1 < E) {
            int2 s = __ldg((const int2*)(ei + e2));
            int2 d = __ldg((const int2*)(ei + E + e2));
            esrc[atomicAdd(&cur[d.x], 1)] = s.x;
            esrc[atomicAdd(&cur[d.y], 1)] = s.y;
        } else if (e2 < E) {
            int s = __ldg(&ei[e2]), d = __ldg(&ei[E + e2]);
            esrc[atomicAdd(&cur[d], 1)] = s;
        }
    } else {
        int i = t - half;   // self loop for node i
        if (i < N) esrc[atomicAdd(&cur[i], 1)] = i;
    }
}

// ===== agg layer1: gather fp16 h1, softmax-avg, +bias, relu, emit fp16 x1 ===
__global__ void agg64_kernel(const int* __restrict__ rowptr,
                             const int* __restrict__ esrc,
                             const float* __restrict__ as,
                             const float* __restrict__ ad,
                             const uint32_t* __restrict__ hh,  // [n,32] fp16x2
                             const float* __restrict__ bias,
                             uint32_t* __restrict__ outh,      // [n,32] fp16x2
                             int n) {
    constexpr int G = 8, EPW = 4;
    int warp = (blockIdx.x * blockDim.x + threadIdx.x) >> 5;
    if (warp >= n) return;
    int lane = threadIdx.x & 31;
    int eslot = lane / G;
    int part = lane % G;

    int beg = __ldg(&rowptr[warp]);
    int end = __ldg(&rowptr[warp + 1]);
    float add = __ldg(&ad[warp]);

    float acc[8] = {0.f, 0.f, 0.f, 0.f, 0.f, 0.f, 0.f, 0.f};
    float den = 0.f;
    for (int i = beg + eslot; i < end; i += EPW) {
        int s = __ldg(&esrc[i]);
        float v = __ldg(&as[s]) + add;
        v = (v > 0.f) ? v : 0.2f * v;
        float w = __expf(v);
        uint4 hv = __ldg((const uint4*)(hh + (size_t)s * 32) + part);
        float2 f0 = h2f(hv.x), f1 = h2f(hv.y), f2 = h2f(hv.z), f3 = h2f(hv.w);
        acc[0] += w * f0.x; acc[1] += w * f0.y;
        acc[2] += w * f1.x; acc[3] += w * f1.y;
        acc[4] += w * f2.x; acc[5] += w * f2.y;
        acc[6] += w * f3.x; acc[7] += w * f3.y;
        den += w;
    }
#pragma unroll
    for (int off = G; off < 32; off <<= 1) {
#pragma unroll
        for (int j = 0; j < 8; j++)
            acc[j] += __shfl_xor_sync(0xffffffffu, acc[j], off);
        den += __shfl_xor_sync(0xffffffffu, den, off);
    }
    if (eslot == 0) {
        float inv = 1.f / den;
        float o[8];
#pragma unroll
        for (int j = 0; j < 8; j++)
            o[j] = fmaxf(acc[j] * inv + __ldg(&bias[part * 8 + j]), 0.f);
        uint4 pk;
        pk.x = fp16x2(o[0], o[1]);
        pk.y = fp16x2(o[2], o[3]);
        pk.z = fp16x2(o[4], o[5]);
        pk.w = fp16x2(o[6], o[7]);
        ((uint4*)(outh + (size_t)warp * 32))[part] = pk;
    }
}

// ===== agg layer2 + head: softmax-avg fp16 h2, +bias, relu, dot Wfc =========
__global__ void agg_final_kernel(const int* __restrict__ rowptr,
                                 const int* __restrict__ esrc,
                                 const float* __restrict__ as,
                                 const float* __restrict__ ad,
                                 const uint32_t* __restrict__ hh,  // [n,16]
                                 const float* __restrict__ b2,
                                 const float* __restrict__ Wfc,
                                 const float* __restrict__ bfc,
                                 float* __restrict__ out, int n) {
    constexpr int G = 4, EPW = 8;
    int warp = (blockIdx.x * blockDim.x + threadIdx.x) >> 5;
    if (warp >= n) return;
    int lane = threadIdx.x & 31;
    int eslot = lane / G;
    int part = lane % G;

    int beg = __ldg(&rowptr[warp]);
    int end = __ldg(&rowptr[warp + 1]);
    float add = __ldg(&ad[warp]);

    float acc[8] = {0.f, 0.f, 0.f, 0.f, 0.f, 0.f, 0.f, 0.f};
    float den = 0.f;
    for (int i = beg + eslot; i < end; i += EPW) {
        int s = __ldg(&esrc[i]);
        float v = __ldg(&as[s]) + add;
        v = (v > 0.f) ? v : 0.2f * v;
        float w = __expf(v);
        uint4 hv = __ldg((const uint4*)(hh + (size_t)s * 16) + part);
        float2 f0 = h2f(hv.x), f1 = h2f(hv.y), f2 = h2f(hv.z), f3 = h2f(hv.w);
        acc[0] += w * f0.x; acc[1] += w * f0.y;
        acc[2] += w * f1.x; acc[3] += w * f1.y;
        acc[4] += w * f2.x; acc[5] += w * f2.y;
        acc[6] += w * f3.x; acc[7] += w * f3.y;
        den += w;
    }
#pragma unroll
    for (int off = G; off < 32; off <<= 1) {
#pragma unroll
        for (int j = 0; j < 8; j++)
            acc[j] += __shfl_xor_sync(0xffffffffu, acc[j], off);
        den += __shfl_xor_sync(0xffffffffu, den, off);
    }
    if (eslot == 0) {  // lanes 0-3
        float inv = 1.f / den;
        float s = 0.f;
#pragma unroll
        for (int j = 0; j < 8; j++) {
            float v = fmaxf(acc[j] * inv + __ldg(&b2[part * 8 + j]), 0.f);
            s += v * __ldg(&Wfc[part * 8 + j]);
        }
        s += __shfl_xor_sync(0x0000000Fu, s, 1);
        s += __shfl_xor_sync(0x0000000Fu, s, 2);
        if (part == 0) out[warp] = s + __ldg(&bfc[0]);
    }
}

// ---------------- launch ----------------
extern "C" void kernel_launch(void* const* d_in, const int* in_sizes, int n_in,
                              void* d_out, int out_size) {
    const float* x   = (const float*)d_in[0];
    const int*   ei  = (const int*)d_in[1];
    const float* W1  = (const float*)d_in[2];
    const float* as1 = (const float*)d_in[3];
    const float* ad1 = (const float*)d_in[4];
    const float* b1  = (const float*)d_in[5];
    const float* W2  = (const float*)d_in[6];
    const float* as2 = (const float*)d_in[7];
    const float* ad2 = (const float*)d_in[8];
    const float* b2  = (const float*)d_in[9];
    const float* Wfc = (const float*)d_in[10];
    const float* bfc = (const float*)d_in[11];
    float* out = (float*)d_out;

    const int N = in_sizes[0] / 256;
    const int E = in_sizes[1] / 2;

    float *asb, *adb;
    uint32_t *h1h, *x1h, *h2h;
    int *deg, *rowptr, *cur, *blk, *esrc;
    uint4 *bf, *bf2;
    cudaGetSymbolAddress((void**)&h1h, g_h1h);
    cudaGetSymbolAddress((void**)&x1h, g_x1h);
    cudaGetSymbolAddress((void**)&h2h, g_h2h);
    cudaGetSymbolAddress((void**)&asb, g_as);
    cudaGetSymbolAddress((void**)&adb, g_ad);
    cudaGetSymbolAddress((void**)&deg, g_deg);
    cudaGetSymbolAddress((void**)&rowptr, g_rowptr);
    cudaGetSymbolAddress((void**)&cur, g_cur);
    cudaGetSymbolAddress((void**)&blk, g_blk);
    cudaGetSymbolAddress((void**)&esrc, g_esrc);
    cudaGetSymbolAddress((void**)&bf, g_bf);
    cudaGetSymbolAddress((void**)&bf2, g_bf2);

    static cudaStream_t s2 = nullptr;
    static cudaEvent_t evFork = nullptr, evJoin = nullptr;
    if (!s2) {
        cudaStreamCreateWithFlags(&s2, cudaStreamNonBlocking);
        cudaEventCreateWithFlags(&evFork, cudaEventDisableTiming);
        cudaEventCreateWithFlags(&evJoin, cudaEventDisableTiming);
    }

    const int T = 256;
    auto nb = [](long long n, int t) { return (int)((n + t - 1) / t); };
    const int nScanBlk = nb(N, 1024);

    // ---------- fork: CSR build starts on side stream ----------
    cudaEventRecord(evFork, 0);
    cudaStreamWaitEvent(s2, evFork, 0);
    cudaMemsetAsync(deg, 0, (size_t)N * sizeof(int), s2);
    hist_kernel<<<nb(((long long)E + 3) / 4, T), T, 0, s2>>>(ei, E, deg);  // 1
    scan_block_kernel<<<nScanBlk, 1024, 0, s2>>>(deg, rowptr, blk, N);     // 2

    // ---------- main stream: preconvert W1, then mma gemm1 (4th launch) ----
    preconv_b_kernel<<<16, 256>>>(W1, bf);                                 // 3
    gemm1_mma_kernel<<<nb(N, 128), 256>>>(x, bf, h1h, N, as1, ad1,
                                          asb, adb);                       // 4

    // ---------- side stream: rest of CSR build + W2 preconvert ----------
    scan_tops_kernel<<<1, 128, 0, s2>>>(blk, nScanBlk);
    scan_add_kernel<<<nScanBlk, 1024, 0, s2>>>(rowptr, blk, deg, cur, N);
    {
        long long scatterThreads = ((long long)E + 1) / 2 + N;
        scatter_kernel<<<nb(scatterThreads, T), T, 0, s2>>>(ei, E, N, cur, esrc);
    }
    preconv_b2_kernel<<<1, 512, 0, s2>>>(W2, bf2);
    cudaEventRecord(evJoin, s2);

    // ---------- join, then layer-1 aggregation (emits fp16 x1) ----------
    cudaStreamWaitEvent(0, evJoin, 0);
    agg64_kernel<<<nb((long long)N * 32, T), T>>>(rowptr, esrc, asb, adb,
                                                  h1h, b1, x1h, N);

    // ---------- layer 2: exact-fp16 MMA gemm, then fused agg+head ----------
    gemm2_mma_kernel<<<nb(N, 128), 256>>>(x1h, bf2, h2h, N, as2, ad2,
                                          asb, adb);
    agg_final_kernel<<<nb((long long)N * 32, T), T>>>(rowptr, esrc, asb, adb,
                                                      h2h, b2, Wfc, bfc,
                                                      out, N);
}

// round 16
// speedup vs baseline: 1.0699x; 1.0249x over previous
#include <cuda_runtime.h>
#include <cuda_bf16.h>
#include <cuda_fp16.h>
#include <cstdint>

#define NN 100000
#define EMAXC 1700000

// ---------------- scratch (static device globals; no allocs) ----------------
__device__ uint32_t g_h1h[NN * 32];  // layer1 features, fp16x2 (64 cols)
__device__ uint32_t g_x1h[NN * 32];  // layer1 output, fp16x2 (64 cols)
__device__ uint32_t g_h2h[NN * 16];  // layer2 features, fp16x2 (32 cols)
__device__ float    g_as[NN];
__device__ float    g_ad[NN];
__device__ int      g_deg[NN];
__device__ int      g_rowptr[NN + 1];
__device__ int      g_cur[NN];
__device__ int      g_blk[128];
__device__ int      g_esrc[EMAXC];
__device__ uint4    g_bf[2048];      // W1 fp16 frags, 2 ntiles/uint4: [kk16][j4][gid8][tig4]
__device__ uint4    g_bf2[256];      // W2 fp16 frags, 2 ntiles/uint4: [kk4][j2][gid8][tig4]

typedef unsigned long long u64;

__device__ __forceinline__ void mma_f16(float* c, uint32_t a0, uint32_t a1,
                                        uint32_t a2, uint32_t a3,
                                        uint32_t b0, uint32_t b1) {
    asm volatile(
        "mma.sync.aligned.m16n8k16.row.col.f32.f16.f16.f32 "
        "{%0,%1,%2,%3}, {%4,%5,%6,%7}, {%8,%9}, {%0,%1,%2,%3};"
        : "+f"(c[0]), "+f"(c[1]), "+f"(c[2]), "+f"(c[3])
        : "r"(a0), "r"(a1), "r"(a2), "r"(a3), "r"(b0), "r"(b1));
}

__device__ __forceinline__ uint32_t fp16x2(float x, float y) {
    __half2 h = __floats2half2_rn(x, y);
    return *(uint32_t*)&h;
}
__device__ __forceinline__ float2 h2f(uint32_t u) {
    return __half22float2(*(__half2*)&u);
}

// W1 frags: entry (kk, j, gid, tig) packs ntiles 2j (n1=16j+gid) and 2j+1
// (n2=16j+8+gid) at k = kk*16 + 2*tig.
__global__ void preconv_b_kernel(const float* __restrict__ W,
                                 uint4* __restrict__ Bf) {
    int idx = blockIdx.x * 256 + threadIdx.x;
    if (idx >= 2048) return;
    int tig = idx & 3, gid = (idx >> 2) & 7, j = (idx >> 5) & 3, kk = idx >> 7;
    int k = kk * 16 + 2 * tig;
    int n1 = j * 16 + gid, n2 = n1 + 8;
    uint4 o;
    o.x = fp16x2(__ldg(&W[(size_t)k * 64 + n1]), __ldg(&W[(size_t)(k + 1) * 64 + n1]));
    o.y = fp16x2(__ldg(&W[(size_t)(k + 8) * 64 + n1]), __ldg(&W[(size_t)(k + 9) * 64 + n1]));
    o.z = fp16x2(__ldg(&W[(size_t)k * 64 + n2]), __ldg(&W[(size_t)(k + 1) * 64 + n2]));
    o.w = fp16x2(__ldg(&W[(size_t)(k + 8) * 64 + n2]), __ldg(&W[(size_t)(k + 9) * 64 + n2]));
    Bf[idx] = o;
}

// W2 frags [64,32]: entry (kk, j, gid, tig) packs n1=16j+gid, n2=16j+8+gid.
__global__ void preconv_b2_kernel(const float* __restrict__ W,
                                  uint4* __restrict__ Bf) {
    int idx = threadIdx.x;
    if (idx >= 256) return;
    int tig = idx & 3, gid = (idx >> 2) & 7, j = (idx >> 5) & 1, kk = idx >> 6;
    int k = kk * 16 + 2 * tig;
    int n1 = j * 16 + gid, n2 = n1 + 8;
    uint4 o;
    o.x = fp16x2(__ldg(&W[(size_t)k * 32 + n1]), __ldg(&W[(size_t)(k + 1) * 32 + n1]));
    o.y = fp16x2(__ldg(&W[(size_t)(k + 8) * 32 + n1]), __ldg(&W[(size_t)(k + 9) * 32 + n1]));
    o.z = fp16x2(__ldg(&W[(size_t)k * 32 + n2]), __ldg(&W[(size_t)(k + 1) * 32 + n2]));
    o.w = fp16x2(__ldg(&W[(size_t)(k + 8) * 32 + n2]), __ldg(&W[(size_t)(k + 9) * 32 + n2]));
    Bf[idx] = o;
}

// ==== gemm1 (16 rows/warp, single-pass fp16 MMA) ===========================
__global__ void __launch_bounds__(256)
gemm1_mma_kernel(const float* __restrict__ A,   // [M,256]
                 const uint4* __restrict__ Bf,
                 uint32_t* __restrict__ Ch,     // [M,32] fp16x2
                 int M,
                 const float* __restrict__ av, const float* __restrict__ bv,
                 float* __restrict__ as_out, float* __restrict__ ad_out) {
    const int tid = threadIdx.x;
    const int wid = tid >> 5, lane = tid & 31;
    const int gid = lane >> 2, tig = lane & 3;
    const int rowBase = blockIdx.x * 128;

    const int grLo = rowBase + wid * 16 + gid;
    const int grHi = grLo + 8;
    const float* a0p = A + (size_t)min(grLo, M - 1) * 256 + 2 * tig;
    const float* a1p = A + (size_t)min(grHi, M - 1) * 256 + 2 * tig;

    float acc[8][4];
#pragma unroll
    for (int t = 0; t < 8; t++)
#pragma unroll
        for (int j = 0; j < 4; j++) acc[t][j] = 0.f;

#pragma unroll 4
    for (int kk = 0; kk < 16; kk++) {
        float2 v00 = __ldg((const float2*)(a0p + kk * 16));
        float2 v01 = __ldg((const float2*)(a0p + kk * 16 + 8));
        float2 v10 = __ldg((const float2*)(a1p + kk * 16));
        float2 v11 = __ldg((const float2*)(a1p + kk * 16 + 8));
        uint32_t a0 = fp16x2(v00.x, v00.y);
        uint32_t a1 = fp16x2(v10.x, v10.y);
        uint32_t a2 = fp16x2(v01.x, v01.y);
        uint32_t a3 = fp16x2(v11.x, v11.y);
        const uint4* bp = Bf + kk * 128 + gid * 4 + tig;
#pragma unroll
        for (int j = 0; j < 4; j++) {
            uint4 b = __ldg(bp + j * 32);
            mma_f16(acc[2 * j], a0, a1, a2, a3, b.x, b.y);
            mma_f16(acc[2 * j + 1], a0, a1, a2, a3, b.z, b.w);
        }
    }

    float sLo = 0.f, dLo = 0.f, sHi = 0.f, dHi = 0.f;
#pragma unroll
    for (int j = 0; j < 4; j++) {
#pragma unroll
        for (int p = 0; p < 2; p++) {
            int nt = 2 * j + p;
            int col = (j * 16 + p * 8) + 2 * tig;   // n = 16j + 8p + gid tile, col within tile
            // NOTE: ntile n-base is 16j+8p; the 8-wide tile covers n-base..n-base+7,
            // this thread's columns are n-base + 2*tig, +1... but MMA n-index maps
            // col = ntile_base + 2*tig (+1). ntile_base = 16*j + 8*p.
            float a0 = __ldg(&av[col]), a1 = __ldg(&av[col + 1]);
            float b0 = __ldg(&bv[col]), b1 = __ldg(&bv[col + 1]);
            float* c = acc[nt];
            if (grLo < M)
                Ch[(size_t)grLo * 32 + (col >> 1)] = fp16x2(c[0], c[1]);
            if (grHi < M)
                Ch[(size_t)grHi * 32 + (col >> 1)] = fp16x2(c[2], c[3]);
            sLo += c[0] * a0 + c[1] * a1;
            dLo += c[0] * b0 + c[1] * b1;
            sHi += c[2] * a0 + c[3] * a1;
            dHi += c[2] * b0 + c[3] * b1;
        }
    }
#pragma unroll
    for (int off = 1; off < 4; off <<= 1) {
        sLo += __shfl_xor_sync(0xffffffffu, sLo, off);
        dLo += __shfl_xor_sync(0xffffffffu, dLo, off);
        sHi += __shfl_xor_sync(0xffffffffu, sHi, off);
        dHi += __shfl_xor_sync(0xffffffffu, dHi, off);
    }
    if (tig == 0) {
        if (grLo < M) { as_out[grLo] = sLo; ad_out[grLo] = dLo; }
        if (grHi < M) { as_out[grHi] = sHi; ad_out[grHi] = dHi; }
    }
}

// ==== gemm2 (single-pass fp16 MMA): h2h = fp16(x1h @ W2) + alphas ==========
__global__ void __launch_bounds__(256)
gemm2_mma_kernel(const uint32_t* __restrict__ A,  // [M,32] fp16x2 (64 cols)
                 const uint4* __restrict__ Bf2,
                 uint32_t* __restrict__ Ch,       // [M,16] fp16x2 (32 cols)
                 int M,
                 const float* __restrict__ av, const float* __restrict__ bv,
                 float* __restrict__ as_out, float* __restrict__ ad_out) {
    const int tid = threadIdx.x;
    const int wid = tid >> 5, lane = tid & 31;
    const int gid = lane >> 2, tig = lane & 3;
    const int rowBase = blockIdx.x * 128;

    const int grLo = rowBase + wid * 16 + gid;
    const int grHi = grLo + 8;
    const uint32_t* a0p = A + (size_t)min(grLo, M - 1) * 32 + tig;
    const uint32_t* a1p = A + (size_t)min(grHi, M - 1) * 32 + tig;

    float acc[4][4];
#pragma unroll
    for (int t = 0; t < 4; t++)
#pragma unroll
        for (int j = 0; j < 4; j++) acc[t][j] = 0.f;

#pragma unroll
    for (int kk = 0; kk < 4; kk++) {
        uint32_t a0 = __ldg(a0p + kk * 8);
        uint32_t a2 = __ldg(a0p + kk * 8 + 4);
        uint32_t a1 = __ldg(a1p + kk * 8);
        uint32_t a3 = __ldg(a1p + kk * 8 + 4);
        const uint4* bp = Bf2 + kk * 64 + gid * 4 + tig;
#pragma unroll
        for (int j = 0; j < 2; j++) {
            uint4 b = __ldg(bp + j * 32);
            mma_f16(acc[2 * j], a0, a1, a2, a3, b.x, b.y);
            mma_f16(acc[2 * j + 1], a0, a1, a2, a3, b.z, b.w);
        }
    }

    float sLo = 0.f, dLo = 0.f, sHi = 0.f, dHi = 0.f;
#pragma unroll
    for (int j = 0; j < 2; j++) {
#pragma unroll
        for (int p = 0; p < 2; p++) {
            int nt = 2 * j + p;
            int col = (j * 16 + p * 8) + 2 * tig;
            float a0 = __ldg(&av[col]), a1 = __ldg(&av[col + 1]);
            float b0 = __ldg(&bv[col]), b1 = __ldg(&bv[col + 1]);
            float* c = acc[nt];
            if (grLo < M)
                Ch[(size_t)grLo * 16 + (col >> 1)] = fp16x2(c[0], c[1]);
            if (grHi < M)
                Ch[(size_t)grHi * 16 + (col >> 1)] = fp16x2(c[2], c[3]);
            sLo += c[0] * a0 + c[1] * a1;
            dLo += c[0] * b0 + c[1] * b1;
            sHi += c[2] * a0 + c[3] * a1;
            dHi += c[2] * b0 + c[3] * b1;
        }
    }
#pragma unroll
    for (int off = 1; off < 4; off <<= 1) {
        sLo += __shfl_xor_sync(0xffffffffu, sLo, off);
        dLo += __shfl_xor_sync(0xffffffffu, dLo, off);
        sHi += __shfl_xor_sync(0xffffffffu, sHi, off);
        dHi += __shfl_xor_sync(0xffffffffu, dHi, off);
    }
    if (tig == 0) {
        if (grLo < M) { as_out[grLo] = sLo; ad_out[grLo] = dLo; }
        if (grHi < M) { as_out[grHi] = sHi; ad_out[grHi] = dHi; }
    }
}

// ======================= CSR build =======================
__global__ void hist_kernel(const int* __restrict__ ei, int E,
                            int* __restrict__ deg) {
    int t = blockIdx.x * blockDim.x + threadIdx.x;
    int e4 = t * 4;
    if (e4 + 3 < E) {
        int4 d = __ldg((const int4*)(ei + E + e4));
        atomicAdd(&deg[d.x], 1);
        atomicAdd(&deg[d.y], 1);
        atomicAdd(&deg[d.z], 1);
        atomicAdd(&deg[d.w], 1);
    } else {
        for (int e = e4; e < E; e++) atomicAdd(&deg[__ldg(&ei[E + e])], 1);
    }
}

__global__ void scan_block_kernel(const int* __restrict__ deg,
                                  int* __restrict__ rowptr,
                                  int* __restrict__ blk, int n) {
    __shared__ int sh[1024];
    int i = blockIdx.x * 1024 + threadIdx.x;
    int v = (i < n) ? deg[i] + 1 : 0;   // +1 = self loop
    sh[threadIdx.x] = v;
    __syncthreads();
#pragma unroll
    for (int off = 1; off < 1024; off <<= 1) {
        int t = (threadIdx.x >= off) ? sh[threadIdx.x - off] : 0;
        __syncthreads();
        sh[threadIdx.x] += t;
        __syncthreads();
    }
    if (i < n) rowptr[i + 1] = sh[threadIdx.x];
    if (threadIdx.x == 1023) blk[blockIdx.x] = sh[1023];
}

__global__ void scan_tops_kernel(int* __restrict__ blk, int nb) {
    __shared__ int sh[128];
    int v = (threadIdx.x < nb) ? blk[threadIdx.x] : 0;
    sh[threadIdx.x] = v;
    __syncthreads();
#pragma unroll
    for (int off = 1; off < 128; off <<= 1) {
        int t = (threadIdx.x >= off) ? sh[threadIdx.x - off] : 0;
        __syncthreads();
        sh[threadIdx.x] += t;
        __syncthreads();
    }
    if (threadIdx.x < nb)
        blk[threadIdx.x] = (threadIdx.x == 0) ? 0 : sh[threadIdx.x - 1];
}

__global__ void scan_add_kernel(int* __restrict__ rowptr,
                                const int* __restrict__ blk,
                                const int* __restrict__ deg,
                                int* __restrict__ cur, int n) {
    int i = blockIdx.x * 1024 + threadIdx.x;
    if (i >= n) return;
    int v = rowptr[i + 1] + blk[i / 1024];
    rowptr[i + 1] = v;
    cur[i] = v - (deg[i] + 1);   // +1 = self loop
    if (i == 0) rowptr[0] = 0;
}

__global__ void scatter_kernel(const int* __restrict__ ei, int E, int N,
                               int* __restrict__ cur, int* __restrict__ esrc) {
    int t = blockIdx.x * blockDim.x + threadIdx.x;
    int half = (E + 1) >> 1;
    if (t < half) {
        int e2 = t * 2;
        if (e2 + 1 < E) {
            int2 s = __ldg((const int2*)(ei + e2));
            int2 d = __ldg((const int2*)(ei + E + e2));
            esrc[atomicAdd(&cur[d.x], 1)] = s.x;
            esrc[atomicAdd(&cur[d.y], 1)] = s.y;
        } else if (e2 < E) {
            int s = __ldg(&ei[e2]), d = __ldg(&ei[E + e2]);
            esrc[atomicAdd(&cur[d], 1)] = s;
        }
    } else {
        int i = t - half;   // self loop for node i
        if (i < N) esrc[atomicAdd(&cur[i], 1)] = i;
    }
}

// ===== agg layer1: gather fp16 h1, softmax-avg, +bias, relu, emit fp16 x1 ===
__global__ void agg64_kernel(const int* __restrict__ rowptr,
                             const int* __restrict__ esrc,
                             const float* __restrict__ as,
                             const float* __restrict__ ad,
                             const uint32_t* __restrict__ hh,  // [n,32] fp16x2
                             const float* __restrict__ bias,
                             uint32_t* __restrict__ outh,      // [n,32] fp16x2
                             int n) {
    constexpr int G = 8, EPW = 4;
    int warp = (blockIdx.x * blockDim.x + threadIdx.x) >> 5;
    if (warp >= n) return;
    int lane = threadIdx.x & 31;
    int eslot = lane / G;
    int part = lane % G;

    int beg = __ldg(&rowptr[warp]);
    int end = __ldg(&rowptr[warp + 1]);
    float add = __ldg(&ad[warp]);

    float acc[8] = {0.f, 0.f, 0.f, 0.f, 0.f, 0.f, 0.f, 0.f};
    float den = 0.f;
    for (int i = beg + eslot; i < end; i += EPW) {
        int s = __ldg(&esrc[i]);
        float v = __ldg(&as[s]) + add;
        v = (v > 0.f) ? v : 0.2f * v;
        float w = __expf(v);
        uint4 hv = __ldg((const uint4*)(hh + (size_t)s * 32) + part);
        float2 f0 = h2f(hv.x), f1 = h2f(hv.y), f2 = h2f(hv.z), f3 = h2f(hv.w);
        acc[0] += w * f0.x; acc[1] += w * f0.y;
        acc[2] += w * f1.x; acc[3] += w * f1.y;
        acc[4] += w * f2.x; acc[5] += w * f2.y;
        acc[6] += w * f3.x; acc[7] += w * f3.y;
        den += w;
    }
#pragma unroll
    for (int off = G; off < 32; off <<= 1) {
#pragma unroll
        for (int j = 0; j < 8; j++)
            acc[j] += __shfl_xor_sync(0xffffffffu, acc[j], off);
        den += __shfl_xor_sync(0xffffffffu, den, off);
    }
    if (eslot == 0) {
        float inv = 1.f / den;
        float o[8];
#pragma unroll
        for (int j = 0; j < 8; j++)
            o[j] = fmaxf(acc[j] * inv + __ldg(&bias[part * 8 + j]), 0.f);
        uint4 pk;
        pk.x = fp16x2(o[0], o[1]);
        pk.y = fp16x2(o[2], o[3]);
        pk.z = fp16x2(o[4], o[5]);
        pk.w = fp16x2(o[6], o[7]);
        ((uint4*)(outh + (size_t)warp * 32))[part] = pk;
    }
}

// ===== agg layer2 + head: softmax-avg fp16 h2, +bias, relu, dot Wfc =========
__global__ void agg_final_kernel(const int* __restrict__ rowptr,
                                 const int* __restrict__ esrc,
                                 const float* __restrict__ as,
                                 const float* __restrict__ ad,
                                 const uint32_t* __restrict__ hh,  // [n,16]
                                 const float* __restrict__ b2,
                                 const float* __restrict__ Wfc,
                                 const float* __restrict__ bfc,
                                 float* __restrict__ out, int n) {
    constexpr int G = 4, EPW = 8;
    int warp = (blockIdx.x * blockDim.x + threadIdx.x) >> 5;
    if (warp >= n) return;
    int lane = threadIdx.x & 31;
    int eslot = lane / G;
    int part = lane % G;

    int beg = __ldg(&rowptr[warp]);
    int end = __ldg(&rowptr[warp + 1]);
    float add = __ldg(&ad[warp]);

    float acc[8] = {0.f, 0.f, 0.f, 0.f, 0.f, 0.f, 0.f, 0.f};
    float den = 0.f;
    for (int i = beg + eslot; i < end; i += EPW) {
        int s = __ldg(&esrc[i]);
        float v = __ldg(&as[s]) + add;
        v = (v > 0.f) ? v : 0.2f * v;
        float w = __expf(v);
        uint4 hv = __ldg((const uint4*)(hh + (size_t)s * 16) + part);
        float2 f0 = h2f(hv.x), f1 = h2f(hv.y), f2 = h2f(hv.z), f3 = h2f(hv.w);
        acc[0] += w * f0.x; acc[1] += w * f0.y;
        acc[2] += w * f1.x; acc[3] += w * f1.y;
        acc[4] += w * f2.x; acc[5] += w * f2.y;
        acc[6] += w * f3.x; acc[7] += w * f3.y;
        den += w;
    }
#pragma unroll
    for (int off = G; off < 32; off <<= 1) {
#pragma unroll
        for (int j = 0; j < 8; j++)
            acc[j] += __shfl_xor_sync(0xffffffffu, acc[j], off);
        den += __shfl_xor_sync(0xffffffffu, den, off);
    }
    if (eslot == 0) {  // lanes 0-3
        float inv = 1.f / den;
        float s = 0.f;
#pragma unroll
        for (int j = 0; j < 8; j++) {
            float v = fmaxf(acc[j] * inv + __ldg(&b2[part * 8 + j]), 0.f);
            s += v * __ldg(&Wfc[part * 8 + j]);
        }
        s += __shfl_xor_sync(0x0000000Fu, s, 1);
        s += __shfl_xor_sync(0x0000000Fu, s, 2);
        if (part == 0) out[warp] = s + __ldg(&bfc[0]);
    }
}

// ---------------- launch ----------------
extern "C" void kernel_launch(void* const* d_in, const int* in_sizes, int n_in,
                              void* d_out, int out_size) {
    const float* x   = (const float*)d_in[0];
    const int*   ei  = (const int*)d_in[1];
    const float* W1  = (const float*)d_in[2];
    const float* as1 = (const float*)d_in[3];
    const float* ad1 = (const float*)d_in[4];
    const float* b1  = (const float*)d_in[5];
    const float* W2  = (const float*)d_in[6];
    const float* as2 = (const float*)d_in[7];
    const float* ad2 = (const float*)d_in[8];
    const float* b2  = (const float*)d_in[9];
    const float* Wfc = (const float*)d_in[10];
    const float* bfc = (const float*)d_in[11];
    float* out = (float*)d_out;

    const int N = in_sizes[0] / 256;
    const int E = in_sizes[1] / 2;

    float *asb, *adb;
    uint32_t *h1h, *x1h, *h2h;
    int *deg, *rowptr, *cur, *blk, *esrc;
    uint4 *bf, *bf2;
    cudaGetSymbolAddress((void**)&h1h, g_h1h);
    cudaGetSymbolAddress((void**)&x1h, g_x1h);
    cudaGetSymbolAddress((void**)&h2h, g_h2h);
    cudaGetSymbolAddress((void**)&asb, g_as);
    cudaGetSymbolAddress((void**)&adb, g_ad);
    cudaGetSymbolAddress((void**)&deg, g_deg);
    cudaGetSymbolAddress((void**)&rowptr, g_rowptr);
    cudaGetSymbolAddress((void**)&cur, g_cur);
    cudaGetSymbolAddress((void**)&blk, g_blk);
    cudaGetSymbolAddress((void**)&esrc, g_esrc);
    cudaGetSymbolAddress((void**)&bf, g_bf);
    cudaGetSymbolAddress((void**)&bf2, g_bf2);

    static cudaStream_t s2 = nullptr;
    static cudaEvent_t evFork = nullptr, evJoin = nullptr;
    if (!s2) {
        cudaStreamCreateWithFlags(&s2, cudaStreamNonBlocking);
        cudaEventCreateWithFlags(&evFork, cudaEventDisableTiming);
        cudaEventCreateWithFlags(&evJoin, cudaEventDisableTiming);
    }

    const int T = 256;
    auto nb = [](long long n, int t) { return (int)((n + t - 1) / t); };
    const int nScanBlk = nb(N, 1024);

    // ---------- fork: CSR build starts on side stream ----------
    cudaEventRecord(evFork, 0);
    cudaStreamWaitEvent(s2, evFork, 0);
    cudaMemsetAsync(deg, 0, (size_t)N * sizeof(int), s2);
    hist_kernel<<<nb(((long long)E + 3) / 4, T), T, 0, s2>>>(ei, E, deg);  // 1
    scan_block_kernel<<<nScanBlk, 1024, 0, s2>>>(deg, rowptr, blk, N);     // 2

    // ---------- main stream: preconvert W1, then mma gemm1 (4th launch) ----
    preconv_b_kernel<<<8, 256>>>(W1, bf);                                  // 3
    gemm1_mma_kernel<<<nb(N, 128), 256>>>(x, bf, h1h, N, as1, ad1,
                                          asb, adb);                       // 4

    // ---------- side stream: rest of CSR build + W2 preconvert ----------
    scan_tops_kernel<<<1, 128, 0, s2>>>(blk, nScanBlk);
    scan_add_kernel<<<nScanBlk, 1024, 0, s2>>>(rowptr, blk, deg, cur, N);
    {
        long long scatterThreads = ((long long)E + 1) / 2 + N;
        scatter_kernel<<<nb(scatterThreads, T), T, 0, s2>>>(ei, E, N, cur, esrc);
    }
    preconv_b2_kernel<<<1, 256, 0, s2>>>(W2, bf2);
    cudaEventRecord(evJoin, s2);

    // ---------- join, then layer-1 aggregation (emits fp16 x1) ----------
    cudaStreamWaitEvent(0, evJoin, 0);
    agg64_kernel<<<nb((long long)N * 32, T), T>>>(rowptr, esrc, asb, adb,
                                                  h1h, b1, x1h, N);

    // ---------- layer 2: single-pass fp16 MMA gemm, then fused agg+head ----
    gemm2_mma_kernel<<<nb(N, 128), 256>>>(x1h, bf2, h2h, N, as2, ad2,
                                          asb, adb);
    agg_final_kernel<<<nb((long long)N * 32, T), T>>>(rowptr, esrc, asb, adb,
                                                      h2h, b2, Wfc, bfc,
                                                      out, N);
}

// round 17
// speedup vs baseline: 1.0880x; 1.0169x over previous
#include <cuda_runtime.h>
#include <cuda_bf16.h>
#include <cuda_fp16.h>
#include <cstdint>

#define NN 100000
#define EMAXC 1700000

// ---------------- scratch (static device globals; no allocs) ----------------
__device__ uint32_t g_h1h[NN * 32];  // layer1 features, fp16x2 (64 cols)
__device__ uint32_t g_x1h[NN * 32];  // layer1 output, fp16x2 (64 cols)
__device__ uint32_t g_h2h[NN * 16];  // layer2 features, fp16x2 (32 cols)
__device__ float    g_as[NN];
__device__ float    g_ad[NN];
__device__ int      g_deg[NN];
__device__ int      g_rowptr[NN + 1];
__device__ int      g_cur[NN];
__device__ int      g_blk[128];
__device__ int      g_esrc[EMAXC];
__device__ uint4    g_bf[2048];      // W1 fp16 frags, 2 ntiles/uint4
__device__ uint4    g_bf2[256];      // W2 fp16 frags, 2 ntiles/uint4

typedef unsigned long long u64;

__device__ __forceinline__ void mma_f16(float* c, uint32_t a0, uint32_t a1,
                                        uint32_t a2, uint32_t a3,
                                        uint32_t b0, uint32_t b1) {
    asm volatile(
        "mma.sync.aligned.m16n8k16.row.col.f32.f16.f16.f32 "
        "{%0,%1,%2,%3}, {%4,%5,%6,%7}, {%8,%9}, {%0,%1,%2,%3};"
        : "+f"(c[0]), "+f"(c[1]), "+f"(c[2]), "+f"(c[3])
        : "r"(a0), "r"(a1), "r"(a2), "r"(a3), "r"(b0), "r"(b1));
}

__device__ __forceinline__ uint32_t fp16x2(float x, float y) {
    __half2 h = __floats2half2_rn(x, y);
    return *(uint32_t*)&h;
}
__device__ __forceinline__ float2 h2f(uint32_t u) {
    return __half22float2(*(__half2*)&u);
}

// Merged W1+W2 fragment preconvert.
// idx < 2048: W1 entry (kk,j,gid,tig): ntiles n1=16j+gid, n2=n1+8, k=16kk+2tig
// idx in [2048,2304): W2 entry, same scheme with 32 cols, j in {0,1}
__global__ void preconv_all_kernel(const float* __restrict__ W1,
                                   const float* __restrict__ W2,
                                   uint4* __restrict__ Bf,
                                   uint4* __restrict__ Bf2) {
    int idx = blockIdx.x * 256 + threadIdx.x;
    if (idx < 2048) {
        int tig = idx & 3, gid = (idx >> 2) & 7, j = (idx >> 5) & 3, kk = idx >> 7;
        int k = kk * 16 + 2 * tig;
        int n1 = j * 16 + gid, n2 = n1 + 8;
        uint4 o;
        o.x = fp16x2(__ldg(&W1[(size_t)k * 64 + n1]), __ldg(&W1[(size_t)(k + 1) * 64 + n1]));
        o.y = fp16x2(__ldg(&W1[(size_t)(k + 8) * 64 + n1]), __ldg(&W1[(size_t)(k + 9) * 64 + n1]));
        o.z = fp16x2(__ldg(&W1[(size_t)k * 64 + n2]), __ldg(&W1[(size_t)(k + 1) * 64 + n2]));
        o.w = fp16x2(__ldg(&W1[(size_t)(k + 8) * 64 + n2]), __ldg(&W1[(size_t)(k + 9) * 64 + n2]));
        Bf[idx] = o;
    } else if (idx < 2304) {
        int i2 = idx - 2048;
        int tig = i2 & 3, gid = (i2 >> 2) & 7, j = (i2 >> 5) & 1, kk = i2 >> 6;
        int k = kk * 16 + 2 * tig;
        int n1 = j * 16 + gid, n2 = n1 + 8;
        uint4 o;
        o.x = fp16x2(__ldg(&W2[(size_t)k * 32 + n1]), __ldg(&W2[(size_t)(k + 1) * 32 + n1]));
        o.y = fp16x2(__ldg(&W2[(size_t)(k + 8) * 32 + n1]), __ldg(&W2[(size_t)(k + 9) * 32 + n1]));
        o.z = fp16x2(__ldg(&W2[(size_t)k * 32 + n2]), __ldg(&W2[(size_t)(k + 1) * 32 + n2]));
        o.w = fp16x2(__ldg(&W2[(size_t)(k + 8) * 32 + n2]), __ldg(&W2[(size_t)(k + 9) * 32 + n2]));
        Bf2[i2] = o;
    }
}

// ==== gemm1 (16 rows/warp, single-pass fp16 MMA), 4 CTAs/SM target =========
__global__ void __launch_bounds__(256, 4)
gemm1_mma_kernel(const float* __restrict__ A,   // [M,256]
                 const uint4* __restrict__ Bf,
                 uint32_t* __restrict__ Ch,     // [M,32] fp16x2
                 int M,
                 const float* __restrict__ av, const float* __restrict__ bv,
                 float* __restrict__ as_out, float* __restrict__ ad_out) {
    const int tid = threadIdx.x;
    const int wid = tid >> 5, lane = tid & 31;
    const int gid = lane >> 2, tig = lane & 3;
    const int rowBase = blockIdx.x * 128;

    const int grLo = rowBase + wid * 16 + gid;
    const int grHi = grLo + 8;
    const float* a0p = A + (size_t)min(grLo, M - 1) * 256 + 2 * tig;
    const float* a1p = A + (size_t)min(grHi, M - 1) * 256 + 2 * tig;

    float acc[8][4];
#pragma unroll
    for (int t = 0; t < 8; t++)
#pragma unroll
        for (int j = 0; j < 4; j++) acc[t][j] = 0.f;

#pragma unroll 4
    for (int kk = 0; kk < 16; kk++) {
        float2 v00 = __ldg((const float2*)(a0p + kk * 16));
        float2 v01 = __ldg((const float2*)(a0p + kk * 16 + 8));
        float2 v10 = __ldg((const float2*)(a1p + kk * 16));
        float2 v11 = __ldg((const float2*)(a1p + kk * 16 + 8));
        uint32_t a0 = fp16x2(v00.x, v00.y);
        uint32_t a1 = fp16x2(v10.x, v10.y);
        uint32_t a2 = fp16x2(v01.x, v01.y);
        uint32_t a3 = fp16x2(v11.x, v11.y);
        const uint4* bp = Bf + kk * 128 + gid * 4 + tig;
#pragma unroll
        for (int j = 0; j < 4; j++) {
            uint4 b = __ldg(bp + j * 32);
            mma_f16(acc[2 * j], a0, a1, a2, a3, b.x, b.y);
            mma_f16(acc[2 * j + 1], a0, a1, a2, a3, b.z, b.w);
        }
    }

    float sLo = 0.f, dLo = 0.f, sHi = 0.f, dHi = 0.f;
#pragma unroll
    for (int j = 0; j < 4; j++) {
#pragma unroll
        for (int p = 0; p < 2; p++) {
            int nt = 2 * j + p;
            int col = (j * 16 + p * 8) + 2 * tig;
            float a0 = __ldg(&av[col]), a1 = __ldg(&av[col + 1]);
            float b0 = __ldg(&bv[col]), b1 = __ldg(&bv[col + 1]);
            float* c = acc[nt];
            if (grLo < M)
                Ch[(size_t)grLo * 32 + (col >> 1)] = fp16x2(c[0], c[1]);
            if (grHi < M)
                Ch[(size_t)grHi * 32 + (col >> 1)] = fp16x2(c[2], c[3]);
            sLo += c[0] * a0 + c[1] * a1;
            dLo += c[0] * b0 + c[1] * b1;
            sHi += c[2] * a0 + c[3] * a1;
            dHi += c[2] * b0 + c[3] * b1;
        }
    }
#pragma unroll
    for (int off = 1; off < 4; off <<= 1) {
        sLo += __shfl_xor_sync(0xffffffffu, sLo, off);
        dLo += __shfl_xor_sync(0xffffffffu, dLo, off);
        sHi += __shfl_xor_sync(0xffffffffu, sHi, off);
        dHi += __shfl_xor_sync(0xffffffffu, dHi, off);
    }
    if (tig == 0) {
        if (grLo < M) { as_out[grLo] = sLo; ad_out[grLo] = dLo; }
        if (grHi < M) { as_out[grHi] = sHi; ad_out[grHi] = dHi; }
    }
}

// ==== gemm2 (single-pass fp16 MMA): h2h = fp16(x1h @ W2) + alphas ==========
__global__ void __launch_bounds__(256)
gemm2_mma_kernel(const uint32_t* __restrict__ A,  // [M,32] fp16x2 (64 cols)
                 const uint4* __restrict__ Bf2,
                 uint32_t* __restrict__ Ch,       // [M,16] fp16x2 (32 cols)
                 int M,
                 const float* __restrict__ av, const float* __restrict__ bv,
                 float* __restrict__ as_out, float* __restrict__ ad_out) {
    const int tid = threadIdx.x;
    const int wid = tid >> 5, lane = tid & 31;
    const int gid = lane >> 2, tig = lane & 3;
    const int rowBase = blockIdx.x * 128;

    const int grLo = rowBase + wid * 16 + gid;
    const int grHi = grLo + 8;
    const uint32_t* a0p = A + (size_t)min(grLo, M - 1) * 32 + tig;
    const uint32_t* a1p = A + (size_t)min(grHi, M - 1) * 32 + tig;

    float acc[4][4];
#pragma unroll
    for (int t = 0; t < 4; t++)
#pragma unroll
        for (int j = 0; j < 4; j++) acc[t][j] = 0.f;

#pragma unroll
    for (int kk = 0; kk < 4; kk++) {
        uint32_t a0 = __ldg(a0p + kk * 8);
        uint32_t a2 = __ldg(a0p + kk * 8 + 4);
        uint32_t a1 = __ldg(a1p + kk * 8);
        uint32_t a3 = __ldg(a1p + kk * 8 + 4);
        const uint4* bp = Bf2 + kk * 64 + gid * 4 + tig;
#pragma unroll
        for (int j = 0; j < 2; j++) {
            uint4 b = __ldg(bp + j * 32);
            mma_f16(acc[2 * j], a0, a1, a2, a3, b.x, b.y);
            mma_f16(acc[2 * j + 1], a0, a1, a2, a3, b.z, b.w);
        }
    }

    float sLo = 0.f, dLo = 0.f, sHi = 0.f, dHi = 0.f;
#pragma unroll
    for (int j = 0; j < 2; j++) {
#pragma unroll
        for (int p = 0; p < 2; p++) {
            int nt = 2 * j + p;
            int col = (j * 16 + p * 8) + 2 * tig;
            float a0 = __ldg(&av[col]), a1 = __ldg(&av[col + 1]);
            float b0 = __ldg(&bv[col]), b1 = __ldg(&bv[col + 1]);
            float* c = acc[nt];
            if (grLo < M)
                Ch[(size_t)grLo * 16 + (col >> 1)] = fp16x2(c[0], c[1]);
            if (grHi < M)
                Ch[(size_t)grHi * 16 + (col >> 1)] = fp16x2(c[2], c[3]);
            sLo += c[0] * a0 + c[1] * a1;
            dLo += c[0] * b0 + c[1] * b1;
            sHi += c[2] * a0 + c[3] * a1;
            dHi += c[2] * b0 + c[3] * b1;
        }
    }
#pragma unroll
    for (int off = 1; off < 4; off <<= 1) {
        sLo += __shfl_xor_sync(0xffffffffu, sLo, off);
        dLo += __shfl_xor_sync(0xffffffffu, dLo, off);
        sHi += __shfl_xor_sync(0xffffffffu, sHi, off);
        dHi += __shfl_xor_sync(0xffffffffu, dHi, off);
    }
    if (tig == 0) {
        if (grLo < M) { as_out[grLo] = sLo; ad_out[grLo] = dLo; }
        if (grHi < M) { as_out[grHi] = sHi; ad_out[grHi] = dHi; }
    }
}

// ======================= CSR build =======================
__global__ void hist_kernel(const int* __restrict__ ei, int E,
                            int* __restrict__ deg) {
    int t = blockIdx.x * blockDim.x + threadIdx.x;
    int e4 = t * 4;
    if (e4 + 3 < E) {
        int4 d = __ldg((const int4*)(ei + E + e4));
        atomicAdd(&deg[d.x], 1);
        atomicAdd(&deg[d.y], 1);
        atomicAdd(&deg[d.z], 1);
        atomicAdd(&deg[d.w], 1);
    } else {
        for (int e = e4; e < E; e++) atomicAdd(&deg[__ldg(&ei[E + e])], 1);
    }
}

__global__ void scan_block_kernel(const int* __restrict__ deg,
                                  int* __restrict__ rowptr,
                                  int* __restrict__ blk, int n) {
    __shared__ int sh[1024];
    int i = blockIdx.x * 1024 + threadIdx.x;
    int v = (i < n) ? deg[i] + 1 : 0;   // +1 = self loop
    sh[threadIdx.x] = v;
    __syncthreads();
#pragma unroll
    for (int off = 1; off < 1024; off <<= 1) {
        int t = (threadIdx.x >= off) ? sh[threadIdx.x - off] : 0;
        __syncthreads();
        sh[threadIdx.x] += t;
        __syncthreads();
    }
    if (i < n) rowptr[i + 1] = sh[threadIdx.x];
    if (threadIdx.x == 1023) blk[blockIdx.x] = sh[1023];
}

// scan_add with fused block-total prefix (one warp self-scans blk[0..bid))
__global__ void scan_add_kernel(int* __restrict__ rowptr,
                                const int* __restrict__ blk,
                                const int* __restrict__ deg,
                                int* __restrict__ cur, int n) {
    __shared__ int baseSh;
    int bid = blockIdx.x;
    if (threadIdx.x < 32) {
        int s = 0;
        for (int j = threadIdx.x; j < bid; j += 32) s += __ldg(&blk[j]);
#pragma unroll
        for (int o = 16; o; o >>= 1) s += __shfl_xor_sync(0xffffffffu, s, o);
        if (threadIdx.x == 0) baseSh = s;
    }
    __syncthreads();
    int base = baseSh;
    int i = bid * 1024 + threadIdx.x;
    if (i >= n) return;
    int v = rowptr[i + 1] + base;
    rowptr[i + 1] = v;
    cur[i] = v - (deg[i] + 1);   // +1 = self loop
    if (i == 0) rowptr[0] = 0;
}

__global__ void scatter_kernel(const int* __restrict__ ei, int E, int N,
                               int* __restrict__ cur, int* __restrict__ esrc) {
    int t = blockIdx.x * blockDim.x + threadIdx.x;
    int half = (E + 1) >> 1;
    if (t < half) {
        int e2 = t * 2;
        if (e2 + 1 < E) {
            int2 s = __ldg((const int2*)(ei + e2));
            int2 d = __ldg((const int2*)(ei + E + e2));
            esrc[atomicAdd(&cur[d.x], 1)] = s.x;
            esrc[atomicAdd(&cur[d.y], 1)] = s.y;
        } else if (e2 < E) {
            int s = __ldg(&ei[e2]), d = __ldg(&ei[E + e2]);
            esrc[atomicAdd(&cur[d], 1)] = s;
        }
    } else {
        int i = t - half;   // self loop for node i
        if (i < N) esrc[atomicAdd(&cur[i], 1)] = i;
    }
}

// ===== agg layer1: gather fp16 h1, softmax-avg, +bias, relu, emit fp16 x1 ===
__global__ void agg64_kernel(const int* __restrict__ rowptr,
                             const int* __restrict__ esrc,
                             const float* __restrict__ as,
                             const float* __restrict__ ad,
                             const uint32_t* __restrict__ hh,  // [n,32] fp16x2
                             const float* __restrict__ bias,
                             uint32_t* __restrict__ outh,      // [n,32] fp16x2
                             int n) {
    constexpr int G = 8, EPW = 4;
    int warp = (blockIdx.x * blockDim.x + threadIdx.x) >> 5;
    if (warp >= n) return;
    int lane = threadIdx.x & 31;
    int eslot = lane / G;
    int part = lane % G;

    int beg = __ldg(&rowptr[warp]);
    int end = __ldg(&rowptr[warp + 1]);
    float add = __ldg(&ad[warp]);

    float acc[8] = {0.f, 0.f, 0.f, 0.f, 0.f, 0.f, 0.f, 0.f};
    float den = 0.f;
    for (int i = beg + eslot; i < end; i += EPW) {
        int s = __ldg(&esrc[i]);
        float v = __ldg(&as[s]) + add;
        v = (v > 0.f) ? v : 0.2f * v;
        float w = __expf(v);
        uint4 hv = __ldg((const uint4*)(hh + (size_t)s * 32) + part);
        float2 f0 = h2f(hv.x), f1 = h2f(hv.y), f2 = h2f(hv.z), f3 = h2f(hv.w);
        acc[0] += w * f0.x; acc[1] += w * f0.y;
        acc[2] += w * f1.x; acc[3] += w * f1.y;
        acc[4] += w * f2.x; acc[5] += w * f2.y;
        acc[6] += w * f3.x; acc[7] += w * f3.y;
        den += w;
    }
#pragma unroll
    for (int off = G; off < 32; off <<= 1) {
#pragma unroll
        for (int j = 0; j < 8; j++)
            acc[j] += __shfl_xor_sync(0xffffffffu, acc[j], off);
        den += __shfl_xor_sync(0xffffffffu, den, off);
    }
    if (eslot == 0) {
        float inv = 1.f / den;
        float o[8];
#pragma unroll
        for (int j = 0; j < 8; j++)
            o[j] = fmaxf(acc[j] * inv + __ldg(&bias[part * 8 + j]), 0.f);
        uint4 pk;
        pk.x = fp16x2(o[0], o[1]);
        pk.y = fp16x2(o[2], o[3]);
        pk.z = fp16x2(o[4], o[5]);
        pk.w = fp16x2(o[6], o[7]);
        ((uint4*)(outh + (size_t)warp * 32))[part] = pk;
    }
}

// ===== agg layer2 + head: softmax-avg fp16 h2, +bias, relu, dot Wfc =========
__global__ void agg_final_kernel(const int* __restrict__ rowptr,
                                 const int* __restrict__ esrc,
                                 const float* __restrict__ as,
                                 const float* __restrict__ ad,
                                 const uint32_t* __restrict__ hh,  // [n,16]
                                 const float* __restrict__ b2,
                                 const float* __restrict__ Wfc,
                                 const float* __restrict__ bfc,
                                 float* __restrict__ out, int n) {
    constexpr int G = 4, EPW = 8;
    int warp = (blockIdx.x * blockDim.x + threadIdx.x) >> 5;
    if (warp >= n) return;
    int lane = threadIdx.x & 31;
    int eslot = lane / G;
    int part = lane % G;

    int beg = __ldg(&rowptr[warp]);
    int end = __ldg(&rowptr[warp + 1]);
    float add = __ldg(&ad[warp]);

    float acc[8] = {0.f, 0.f, 0.f, 0.f, 0.f, 0.f, 0.f, 0.f};
    float den = 0.f;
    for (int i = beg + eslot; i < end; i += EPW) {
        int s = __ldg(&esrc[i]);
        float v = __ldg(&as[s]) + add;
        v = (v > 0.f) ? v : 0.2f * v;
        float w = __expf(v);
        uint4 hv = __ldg((const uint4*)(hh + (size_t)s * 16) + part);
        float2 f0 = h2f(hv.x), f1 = h2f(hv.y), f2 = h2f(hv.z), f3 = h2f(hv.w);
        acc[0] += w * f0.x; acc[1] += w * f0.y;
        acc[2] += w * f1.x; acc[3] += w * f1.y;
        acc[4] += w * f2.x; acc[5] += w * f2.y;
        acc[6] += w * f3.x; acc[7] += w * f3.y;
        den += w;
    }
#pragma unroll
    for (int off = G; off < 32; off <<= 1) {
#pragma unroll
        for (int j = 0; j < 8; j++)
            acc[j] += __shfl_xor_sync(0xffffffffu, acc[j], off);
        den += __shfl_xor_sync(0xffffffffu, den, off);
    }
    if (eslot == 0) {  // lanes 0-3
        float inv = 1.f / den;
        float s = 0.f;
#pragma unroll
        for (int j = 0; j < 8; j++) {
            float v = fmaxf(acc[j] * inv + __ldg(&b2[part * 8 + j]), 0.f);
            s += v * __ldg(&Wfc[part * 8 + j]);
        }
        s += __shfl_xor_sync(0x0000000Fu, s, 1);
        s += __shfl_xor_sync(0x0000000Fu, s, 2);
        if (part == 0) out[warp] = s + __ldg(&bfc[0]);
    }
}

// ---------------- launch ----------------
extern "C" void kernel_launch(void* const* d_in, const int* in_sizes, int n_in,
                              void* d_out, int out_size) {
    const float* x   = (const float*)d_in[0];
    const int*   ei  = (const int*)d_in[1];
    const float* W1  = (const float*)d_in[2];
    const float* as1 = (const float*)d_in[3];
    const float* ad1 = (const float*)d_in[4];
    const float* b1  = (const float*)d_in[5];
    const float* W2  = (const float*)d_in[6];
    const float* as2 = (const float*)d_in[7];
    const float* ad2 = (const float*)d_in[8];
    const float* b2  = (const float*)d_in[9];
    const float* Wfc = (const float*)d_in[10];
    const float* bfc = (const float*)d_in[11];
    float* out = (float*)d_out;

    const int N = in_sizes[0] / 256;
    const int E = in_sizes[1] / 2;

    float *asb, *adb;
    uint32_t *h1h, *x1h, *h2h;
    int *deg, *rowptr, *cur, *blk, *esrc;
    uint4 *bf, *bf2;
    cudaGetSymbolAddress((void**)&h1h, g_h1h);
    cudaGetSymbolAddress((void**)&x1h, g_x1h);
    cudaGetSymbolAddress((void**)&h2h, g_h2h);
    cudaGetSymbolAddress((void**)&asb, g_as);
    cudaGetSymbolAddress((void**)&adb, g_ad);
    cudaGetSymbolAddress((void**)&deg, g_deg);
    cudaGetSymbolAddress((void**)&rowptr, g_rowptr);
    cudaGetSymbolAddress((void**)&cur, g_cur);
    cudaGetSymbolAddress((void**)&blk, g_blk);
    cudaGetSymbolAddress((void**)&esrc, g_esrc);
    cudaGetSymbolAddress((void**)&bf, g_bf);
    cudaGetSymbolAddress((void**)&bf2, g_bf2);

    static cudaStream_t s2 = nullptr;
    static cudaEvent_t evFork = nullptr, evJoin = nullptr;
    if (!s2) {
        cudaStreamCreateWithFlags(&s2, cudaStreamNonBlocking);
        cudaEventCreateWithFlags(&evFork, cudaEventDisableTiming);
        cudaEventCreateWithFlags(&evJoin, cudaEventDisableTiming);
    }

    const int T = 256;
    auto nb = [](long long n, int t) { return (int)((n + t - 1) / t); };
    const int nScanBlk = nb(N, 1024);

    // ---------- fork: CSR build starts on side stream ----------
    cudaEventRecord(evFork, 0);
    cudaStreamWaitEvent(s2, evFork, 0);
    cudaMemsetAsync(deg, 0, (size_t)N * sizeof(int), s2);
    hist_kernel<<<nb(((long long)E + 3) / 4, T), T, 0, s2>>>(ei, E, deg);  // 1
    scan_block_kernel<<<nScanBlk, 1024, 0, s2>>>(deg, rowptr, blk, N);     // 2

    // ---------- main stream: merged preconv, then mma gemm1 (4th launch) ---
    preconv_all_kernel<<<9, 256>>>(W1, W2, bf, bf2);                       // 3
    gemm1_mma_kernel<<<nb(N, 128), 256>>>(x, bf, h1h, N, as1, ad1,
                                          asb, adb);                       // 4

    // ---------- side stream: rest of CSR build ----------
    scan_add_kernel<<<nScanBlk, 1024, 0, s2>>>(rowptr, blk, deg, cur, N);  // 5
    {
        long long scatterThreads = ((long long)E + 1) / 2 + N;
        scatter_kernel<<<nb(scatterThreads, T), T, 0, s2>>>(ei, E, N, cur, esrc); // 6
    }
    cudaEventRecord(evJoin, s2);

    // ---------- join, then layer-1 aggregation (emits fp16 x1) ----------
    cudaStreamWaitEvent(0, evJoin, 0);
    agg64_kernel<<<nb((long long)N * 32, T), T>>>(rowptr, esrc, asb, adb,
                                                  h1h, b1, x1h, N);        // 7

    // ---------- layer 2: single-pass fp16 MMA gemm, then fused agg+head ----
    gemm2_mma_kernel<<<nb(N, 128), 256>>>(x1h, bf2, h2h, N, as2, ad2,
                                          asb, adb);                       // 8
    agg_final_kernel<<<nb((long long)N * 32, T), T>>>(rowptr, esrc, asb, adb,
                                                      h2h, b2, Wfc, bfc,
                                                      out, N);             // 9
}